// round 1
// baseline (speedup 1.0000x reference)
#include <cuda_runtime.h>
#include <math.h>

// ---------------- problem constants ----------------
#define DIMC  128
#define TT    16
#define HH    32
#define WWD   32
#define BBATCH 8
#define INNER 256
#define NHEAD 4
#define DHEAD 64
#define SEQS  (BBATCH*HH*WWD)   // 8192
#define ROWS  (SEQS*TT)         // 131072
#define UPCOLS 512

// ---------------- scratch (static device, no allocs) ----------------
__device__ float g_XS[(size_t)ROWS*DIMC];    // 67 MB  [row][c]
__device__ float g_UP[(size_t)ROWS*UPCOLS];  // 268 MB [row][512]
__device__ float g_HS[(size_t)ROWS*INNER];   // 134 MB [row][256]
__device__ float g_OT[(size_t)ROWS*DIMC];    // 67 MB  [row][128]

// ---------------- helpers ----------------
__device__ __forceinline__ float siluf(float x){ return x / (1.f + expf(-x)); }
__device__ __forceinline__ float lsig(float x){ return fminf(x,0.f) - log1pf(expf(-fabsf(x))); }

// ---------------- kernel 1: (b,c,t,h,w) -> XS[seq= b*1024+h*32+w][t][c] ----------------
__global__ void __launch_bounds__(256) k_transpose_in(const float* __restrict__ x,
                                                      float* __restrict__ XS) {
    __shared__ float tile[128*33];
    int bid = blockIdx.x;            // (b, t, h)
    int b = bid >> 9;
    int t = (bid >> 5) & 15;
    int h = bid & 31;
    const float* src = x + ((size_t)(b*128)*16 + t) * 1024 + h*32;   // + c*16384 + w
    for (int idx = threadIdx.x; idx < 128*32; idx += 256) {
        int c = idx >> 5, w = idx & 31;
        tile[c*33 + w] = src[(size_t)c*16384 + w];
    }
    __syncthreads();
    size_t base = ((size_t)(b*1024 + h*32) * 16 + t) * 128;          // + w*2048 + c
    for (int idx = threadIdx.x; idx < 32*128; idx += 256) {
        int w = idx >> 7, c = idx & 127;
        XS[base + (size_t)w*2048 + c] = tile[c*33 + w];
    }
}

// ---------------- kernel 5: OT[row][c] -> out (b,c,t,h,w) ----------------
__global__ void __launch_bounds__(256) k_transpose_out(const float* __restrict__ OT,
                                                       float* __restrict__ out) {
    __shared__ float tile[128*33];
    int bid = blockIdx.x;
    int b = bid >> 9;
    int t = (bid >> 5) & 15;
    int h = bid & 31;
    size_t base = ((size_t)(b*1024 + h*32) * 16 + t) * 128;
    for (int idx = threadIdx.x; idx < 32*128; idx += 256) {
        int w = idx >> 7, c = idx & 127;
        tile[c*33 + w] = OT[base + (size_t)w*2048 + c];
    }
    __syncthreads();
    float* dst = out + ((size_t)(b*128)*16 + t) * 1024 + h*32;
    for (int idx = threadIdx.x; idx < 128*32; idx += 256) {
        int c = idx >> 5, w = idx & 31;
        dst[(size_t)c*16384 + w] = tile[c*33 + w];
    }
}

// ---------------- fp32 SGEMM: C[M,N] = A[M,K] @ B[K,N] ----------------
// BM=BN=128, BK=16, 256 threads, 8x8 register tiles. M%128==0, N%128==0, K%16==0.
__global__ void __launch_bounds__(256) k_sgemm(const float* __restrict__ A,
                                               const float* __restrict__ B,
                                               float* __restrict__ C,
                                               int M, int N, int K) {
    __shared__ float As[16*128];
    __shared__ float Bs[16*128];
    int tid = threadIdx.x;
    int tx = tid & 15, ty = tid >> 4;
    int row0 = blockIdx.y * 128, col0 = blockIdx.x * 128;
    float acc[8][8];
#pragma unroll
    for (int i = 0; i < 8; i++)
#pragma unroll
        for (int j = 0; j < 8; j++) acc[i][j] = 0.f;

    for (int k0 = 0; k0 < K; k0 += 16) {
#pragma unroll
        for (int i = 0; i < 2; i++) {
            int f = tid + 256*i;              // 0..511
            int r = f >> 2;                   // row within tile
            int kq = (f & 3) << 2;            // 0,4,8,12
            float4 v = *(const float4*)(A + (size_t)(row0 + r)*K + k0 + kq);
            As[(kq+0)*128 + r] = v.x;
            As[(kq+1)*128 + r] = v.y;
            As[(kq+2)*128 + r] = v.z;
            As[(kq+3)*128 + r] = v.w;
        }
#pragma unroll
        for (int i = 0; i < 2; i++) {
            int f = tid + 256*i;
            int kk = f >> 5;                  // 0..15
            int nq = (f & 31) << 2;
            *(float4*)(Bs + kk*128 + nq) =
                *(const float4*)(B + (size_t)(k0 + kk)*N + col0 + nq);
        }
        __syncthreads();
#pragma unroll
        for (int kk = 0; kk < 16; kk++) {
            float a[8], bb[8];
#pragma unroll
            for (int i = 0; i < 8; i++) a[i] = As[kk*128 + ty*8 + i];
#pragma unroll
            for (int j = 0; j < 8; j++) bb[j] = Bs[kk*128 + tx*8 + j];
#pragma unroll
            for (int i = 0; i < 8; i++)
#pragma unroll
                for (int j = 0; j < 8; j++)
                    acc[i][j] += a[i] * bb[j];
        }
        __syncthreads();
    }
#pragma unroll
    for (int i = 0; i < 8; i++) {
        size_t r = (size_t)(row0 + ty*8 + i);
        float4 v0 = make_float4(acc[i][0], acc[i][1], acc[i][2], acc[i][3]);
        float4 v1 = make_float4(acc[i][4], acc[i][5], acc[i][6], acc[i][7]);
        *(float4*)(C + r*N + col0 + tx*8)     = v0;
        *(float4*)(C + r*N + col0 + tx*8 + 4) = v1;
    }
}

// ---------------- kernel 3: per-sequence fused middle ----------------
// smem layout (floats)
#define S_UP  0        // [16][512]
#define S_XC  8192     // [16][256]
#define S_QT  12288    // q transposed: [i=0..255][t], stride 17
#define S_K   16640    // [t][266]
#define S_V   20896    // [t][266]
#define S_HT  25152    // hs transposed: [i][s], stride 17
#define S_IG  29504    // [t][4]
#define S_FG  29568    // [t][4]
#define S_LFC 29632    // [h][17]
#define S_AA  29700    // [h][16]  a[t] = ig[t] - lfc[t+1]
#define S_WM  29764    // [h][s][t] = 4*16*16
#define SM3_FLOATS 30788

__global__ void __launch_bounds__(256) k_seq(
    const float* __restrict__ UP,
    const float* __restrict__ conv_w, const float* __restrict__ conv_b,
    const float* __restrict__ Wq, const float* __restrict__ Wk, const float* __restrict__ Wv,
    const float* __restrict__ ig_w, const float* __restrict__ ig_b,
    const float* __restrict__ fg_w, const float* __restrict__ fg_b,
    const float* __restrict__ ln_w, const float* __restrict__ skip,
    float* __restrict__ HS) {
    extern __shared__ float sm[];
    const int tid = threadIdx.x;
    const int seq = blockIdx.x;

    // --- load UP rows [16][512] ---
    {
        const float4* src = (const float4*)(UP + (size_t)seq * 16 * 512);
        float4* d4 = (float4*)(sm + S_UP);
        for (int i = tid; i < 2048; i += 256) d4[i] = src[i];
    }
    __syncthreads();

    // --- causal depthwise conv (K=4) + silu -> xc ---
    for (int e = tid; e < 4096; e += 256) {
        int t = e >> 8, i = e & 255;
        float a = conv_b[i];
#pragma unroll
        for (int j = 0; j < 4; j++) {
            int tt = t + j - 3;
            if (tt >= 0) a += conv_w[j*256 + i] * sm[S_UP + tt*512 + i];
        }
        sm[S_XC + t*256 + i] = siluf(a);
    }
    __syncthreads();

    // --- block-diagonal q,k,v (4x4 blocks) ---
    for (int e = tid; e < 4096; e += 256) {
        int t = e >> 8, col = e & 255;
        int n = col >> 2, o = col & 3;
        const float* wq = Wq + n*16 + o*4;
        const float* wk = Wk + n*16 + o*4;
        const float* wv = Wv + n*16 + o*4;
        float aq = 0.f, ak = 0.f, av = 0.f;
#pragma unroll
        for (int i2 = 0; i2 < 4; i2++) {
            float xcv = sm[S_XC + t*256 + n*4 + i2];
            float xmv = sm[S_UP + t*512 + n*4 + i2];
            aq += xcv * wq[i2];
            ak += xcv * wk[i2];
            av += xmv * wv[i2];
        }
        sm[S_QT + col*17 + t]  = aq;
        sm[S_K  + t*266 + col] = ak;
        sm[S_V  + t*266 + col] = av;
    }
    __syncthreads();

    // --- gate preacts ig/fg: thread -> (half, h, t, gate) ---
    {
        int half = tid & 1, gh = (tid >> 1) & 3, gt = (tid >> 3) & 15, gate = (tid >> 7) & 1;
        const float* gw = gate ? fg_w : ig_w;
        float a = 0.f;
        int j0 = half * 384;
        for (int jj = j0; jj < j0 + 384; jj++) {
            float v;
            if (jj < 256)      v = sm[S_QT + jj*17 + gt];
            else if (jj < 512) v = sm[S_K + gt*266 + (jj - 256)];
            else               v = sm[S_V + gt*266 + (jj - 512)];
            a += v * gw[jj*4 + gh];
        }
        a += __shfl_xor_sync(0xffffffffu, a, 1);
        if (half == 0) {
            float bias = gate ? fg_b[gh] : ig_b[gh];
            sm[(gate ? S_FG : S_IG) + gt*4 + gh] = a + bias;
        }
    }
    __syncthreads();

    // --- per-head cumulative log-forget + a[t] (serial, tiny) ---
    if (tid < 4) {
        int hh2 = tid;
        float cum = 0.f;
        sm[S_LFC + hh2*17 + 0] = 0.f;
        for (int t = 0; t < 16; t++) {
            cum += lsig(sm[S_FG + t*4 + hh2]);
            sm[S_LFC + hh2*17 + t + 1] = cum;
            sm[S_AA + hh2*16 + t] = sm[S_IG + t*4 + hh2] - cum;
        }
    }

    // --- qk: thread -> (h, s, tq), covers t = tq*4..tq*4+3 ---
    const int mh = tid >> 6;            // head
    const int ms = (tid >> 2) & 15;     // query position s
    const int mtq = tid & 3;            // t quarter
    float qk0 = 0.f, qk1 = 0.f, qk2 = 0.f, qk3 = 0.f;
    {
        int qtb = mh*64*17 + ms;
        int kb = (mtq*4)*266 + mh*64;
#pragma unroll 4
        for (int d = 0; d < 64; d++) {
            float qv = sm[S_QT + qtb + d*17];
            qk0 += qv * sm[S_K + kb +       d];
            qk1 += qv * sm[S_K + kb + 266 + d];
            qk2 += qv * sm[S_K + kb + 532 + d];
            qk3 += qv * sm[S_K + kb + 798 + d];
        }
    }
    __syncthreads();   // lfc/a visible

    // --- D-weights + normalizer -> wm ---
    {
        float qks[4] = {qk0*0.125f, qk1*0.125f, qk2*0.125f, qk3*0.125f};
        float cs = sm[S_LFC + mh*17 + ms + 1];
        float mloc = -1e30f;
        float ldv[4];
#pragma unroll
        for (int j = 0; j < 4; j++) {
            int t = mtq*4 + j;
            if (t <= ms) { ldv[j] = cs + sm[S_AA + mh*16 + t]; mloc = fmaxf(mloc, ldv[j]); }
            else ldv[j] = 0.f;
        }
        mloc = fmaxf(mloc, __shfl_xor_sync(0xffffffffu, mloc, 1));
        mloc = fmaxf(mloc, __shfl_xor_sync(0xffffffffu, mloc, 2));
        float cv[4]; float csum = 0.f;
#pragma unroll
        for (int j = 0; j < 4; j++) {
            int t = mtq*4 + j;
            cv[j] = (t <= ms) ? qks[j] * expf(ldv[j] - mloc) : 0.f;
            csum += cv[j];
        }
        csum += __shfl_xor_sync(0xffffffffu, csum, 1);
        csum += __shfl_xor_sync(0xffffffffu, csum, 2);
        float norm = fmaxf(fabsf(csum), expf(-mloc)) + 1e-6f;
        float inv = 1.f / norm;
#pragma unroll
        for (int j = 0; j < 4; j++)
            sm[S_WM + (mh*16 + ms)*16 + mtq*4 + j] = cv[j] * inv;
    }
    __syncthreads();

    // --- out = wm @ v : thread -> (h, d) computes all 16 s ---
    {
        int hC = tid >> 6, dC = tid & 63;
        float vreg[16];
#pragma unroll
        for (int t = 0; t < 16; t++) vreg[t] = sm[S_V + t*266 + hC*64 + dC];
#pragma unroll
        for (int s2 = 0; s2 < 16; s2++) {
            float a2 = 0.f;
#pragma unroll
            for (int t = 0; t < 16; t++)
                a2 += sm[S_WM + (hC*16 + s2)*16 + t] * vreg[t];
            sm[S_HT + (hC*64 + dC)*17 + s2] = a2;
        }
    }
    __syncthreads();

    // --- group LayerNorm + skip*xc + silu(z) gate ---
    {
        int hD = tid >> 6, sD = (tid >> 2) & 15, dq = tid & 3;
        float vals[16]; float sum = 0.f, sq = 0.f;
#pragma unroll
        for (int dd = 0; dd < 16; dd++) {
            int i = hD*64 + dq*16 + dd;
            float v = sm[S_HT + i*17 + sD];
            vals[dd] = v; sum += v; sq += v*v;
        }
        sum += __shfl_xor_sync(0xffffffffu, sum, 1);
        sum += __shfl_xor_sync(0xffffffffu, sum, 2);
        sq  += __shfl_xor_sync(0xffffffffu, sq, 1);
        sq  += __shfl_xor_sync(0xffffffffu, sq, 2);
        float mu = sum * (1.f/64.f);
        float var = sq * (1.f/64.f) - mu*mu;
        float rstd = rsqrtf(var + 1e-5f);
#pragma unroll
        for (int dd = 0; dd < 16; dd++) {
            int i = hD*64 + dq*16 + dd;
            float hn = (vals[dd] - mu) * rstd * ln_w[i];
            float zz = sm[S_UP + sD*512 + 256 + i];
            float o = (hn + skip[i] * sm[S_XC + sD*256 + i]) * siluf(zz);
            sm[S_HT + i*17 + sD] = o;
        }
    }
    __syncthreads();

    // --- coalesced write HS[row][i] ---
    {
        float* dst = HS + (size_t)seq * 16 * 256;
        for (int idx = tid; idx < 4096; idx += 256) {
            int t = idx >> 8, i = idx & 255;
            dst[idx] = sm[S_HT + i*17 + t];
        }
    }
}

// ---------------- launch ----------------
extern "C" void kernel_launch(void* const* d_in, const int* in_sizes, int n_in,
                              void* d_out, int out_size) {
    const float* x      = (const float*)d_in[0];
    const float* W_up   = (const float*)d_in[1];
    const float* conv_w = (const float*)d_in[2];
    const float* conv_b = (const float*)d_in[3];
    const float* Wq     = (const float*)d_in[4];
    const float* Wk     = (const float*)d_in[5];
    const float* Wv     = (const float*)d_in[6];
    const float* ig_w   = (const float*)d_in[7];
    const float* ig_b   = (const float*)d_in[8];
    const float* fg_w   = (const float*)d_in[9];
    const float* fg_b   = (const float*)d_in[10];
    const float* ln_w   = (const float*)d_in[11];
    const float* skip   = (const float*)d_in[12];
    const float* W_down = (const float*)d_in[13];
    float* out = (float*)d_out;

    float *XS, *UP, *HS, *OT;
    cudaGetSymbolAddress((void**)&XS, g_XS);
    cudaGetSymbolAddress((void**)&UP, g_UP);
    cudaGetSymbolAddress((void**)&HS, g_HS);
    cudaGetSymbolAddress((void**)&OT, g_OT);

    cudaFuncSetAttribute(k_seq, cudaFuncAttributeMaxDynamicSharedMemorySize,
                         SM3_FLOATS * (int)sizeof(float));

    k_transpose_in<<<4096, 256>>>(x, XS);
    k_sgemm<<<dim3(4, 1024), 256>>>(XS, W_up, UP, ROWS, 512, 128);
    k_seq<<<SEQS, 256, SM3_FLOATS * sizeof(float)>>>(UP, conv_w, conv_b,
        Wq, Wk, Wv, ig_w, ig_b, fg_w, fg_b, ln_w, skip, HS);
    k_sgemm<<<dim3(1, 1024), 256>>>(HS, W_down, OT, ROWS, 128, 256);
    k_transpose_out<<<4096, 256>>>(OT, out);
}

// round 4
// speedup vs baseline: 1.7836x; 1.7836x over previous
#include <cuda_runtime.h>
#include <cstdint>
#include <math.h>

// ---------------- problem constants ----------------
#define DIMC  128
#define TT    16
#define INNER 256
#define SEQS  8192
#define ROWS  (SEQS*TT)         // 131072
#define UPCOLS 512

// ---------------- scratch (static device, no allocs) ----------------
__device__ float g_XS[(size_t)ROWS*DIMC];    // [row][128]
__device__ float g_UP[(size_t)ROWS*UPCOLS];  // [row][512]
__device__ float g_HS[(size_t)ROWS*INNER];   // [row][256]
__device__ float g_OT[(size_t)ROWS*DIMC];    // [row][128]
__device__ float g_WTU[512*128];             // W_up^T  [n][k]
__device__ float g_WTD[128*256];             // W_down^T [n][k]

// ---------------- helpers ----------------
__device__ __forceinline__ float siluf(float x){ return x / (1.f + expf(-x)); }
__device__ __forceinline__ float lsig(float x){ return fminf(x,0.f) - log1pf(expf(-fabsf(x))); }
__device__ __forceinline__ uint32_t f2tf32(float f){
    uint32_t o; asm("cvt.rna.tf32.f32 %0, %1;" : "=r"(o) : "f"(f)); return o;
}

// ---------------- kernel: (b,c,t,h,w) -> XS[seq][t][c] ----------------
__global__ void __launch_bounds__(256) k_transpose_in(const float* __restrict__ x,
                                                      float* __restrict__ XS) {
    __shared__ float tile[128*33];
    int bid = blockIdx.x;
    int b = bid >> 9;
    int t = (bid >> 5) & 15;
    int h = bid & 31;
    const float* src = x + ((size_t)(b*128)*16 + t) * 1024 + h*32;
    for (int idx = threadIdx.x; idx < 128*32; idx += 256) {
        int c = idx >> 5, w = idx & 31;
        tile[c*33 + w] = src[(size_t)c*16384 + w];
    }
    __syncthreads();
    size_t base = ((size_t)(b*1024 + h*32) * 16 + t) * 128;
    for (int idx = threadIdx.x; idx < 32*128; idx += 256) {
        int w = idx >> 7, c = idx & 127;
        XS[base + (size_t)w*2048 + c] = tile[c*33 + w];
    }
}

// ---------------- kernel: OT[row][c] -> out (b,c,t,h,w) ----------------
__global__ void __launch_bounds__(256) k_transpose_out(const float* __restrict__ OT,
                                                       float* __restrict__ out) {
    __shared__ float tile[128*33];
    int bid = blockIdx.x;
    int b = bid >> 9;
    int t = (bid >> 5) & 15;
    int h = bid & 31;
    size_t base = ((size_t)(b*1024 + h*32) * 16 + t) * 128;
    for (int idx = threadIdx.x; idx < 32*128; idx += 256) {
        int w = idx >> 7, c = idx & 127;
        tile[c*33 + w] = OT[base + (size_t)w*2048 + c];
    }
    __syncthreads();
    float* dst = out + ((size_t)(b*128)*16 + t) * 1024 + h*32;
    for (int idx = threadIdx.x; idx < 128*32; idx += 256) {
        int c = idx >> 5, w = idx & 31;
        dst[(size_t)c*16384 + w] = tile[c*33 + w];
    }
}

// ---------------- weight transpose: Wt[n][k] = W[k][n] ----------------
__global__ void k_wt(const float* __restrict__ W, float* __restrict__ Wt, int K, int N){
    int idx = blockIdx.x*256 + threadIdx.x;
    if (idx < K*N) { int k = idx / N, n = idx - k*N; Wt[(size_t)n*K + k] = W[idx]; }
}

// ---------------- TF32 warp-MMA GEMM: C[M,Ng] = A[M,K] @ Bt[Ng,K]^T ----------------
// CTA tile 128x128, BK=32, 8 warps each 32(m) x 64(n), m16n8k8 tf32 fragments.
// smem row stride 36 floats (36 mod 32 == 4 -> conflict-free fragment loads).
__global__ void __launch_bounds__(256) k_gemm_mma(const float* __restrict__ A,
        const float* __restrict__ Bt, float* __restrict__ C, int Ng, int Kf) {
    __shared__ uint32_t As[128*36];
    __shared__ uint32_t Bs[128*36];
    const int tid  = threadIdx.x;
    const int lane = tid & 31, warp = tid >> 5;
    const int gid  = lane >> 2, tig = lane & 3;
    const int wm0  = (warp >> 1) * 32;
    const int wn0  = (warp & 1) * 64;
    const int m0 = blockIdx.y * 128, n0 = blockIdx.x * 128;

    float acc[2][8][4];
#pragma unroll
    for (int i = 0; i < 2; i++)
#pragma unroll
        for (int j = 0; j < 8; j++)
#pragma unroll
            for (int e = 0; e < 4; e++) acc[i][j][e] = 0.f;

    for (int kb = 0; kb < Kf; kb += 32) {
        __syncthreads();
#pragma unroll
        for (int r = 0; r < 4; r++) {
            int f = tid + 256*r;
            int row = f >> 3, q = (f & 7) << 2;
            float4 va = *(const float4*)(A  + (size_t)(m0+row)*Kf + kb + q);
            float4 vb = *(const float4*)(Bt + (size_t)(n0+row)*Kf + kb + q);
            uint32_t* pa = &As[row*36 + q];
            uint32_t* pb = &Bs[row*36 + q];
            pa[0] = f2tf32(va.x); pa[1] = f2tf32(va.y);
            pa[2] = f2tf32(va.z); pa[3] = f2tf32(va.w);
            pb[0] = f2tf32(vb.x); pb[1] = f2tf32(vb.y);
            pb[2] = f2tf32(vb.z); pb[3] = f2tf32(vb.w);
        }
        __syncthreads();
#pragma unroll
        for (int ks = 0; ks < 4; ks++) {
            const int k = ks*8;
            uint32_t a[2][4], b[8][2];
#pragma unroll
            for (int i = 0; i < 2; i++) {
                int r = wm0 + i*16 + gid;
                a[i][0] = As[r*36 + k + tig];
                a[i][1] = As[(r+8)*36 + k + tig];
                a[i][2] = As[r*36 + k + tig + 4];
                a[i][3] = As[(r+8)*36 + k + tig + 4];
            }
#pragma unroll
            for (int j = 0; j < 8; j++) {
                int r = wn0 + j*8 + gid;
                b[j][0] = Bs[r*36 + k + tig];
                b[j][1] = Bs[r*36 + k + tig + 4];
            }
#pragma unroll
            for (int i = 0; i < 2; i++)
#pragma unroll
                for (int j = 0; j < 8; j++)
                    asm volatile(
                        "mma.sync.aligned.m16n8k8.row.col.f32.tf32.tf32.f32 "
                        "{%0,%1,%2,%3}, {%4,%5,%6,%7}, {%8,%9}, {%0,%1,%2,%3};"
                        : "+f"(acc[i][j][0]), "+f"(acc[i][j][1]),
                          "+f"(acc[i][j][2]), "+f"(acc[i][j][3])
                        : "r"(a[i][0]), "r"(a[i][1]), "r"(a[i][2]), "r"(a[i][3]),
                          "r"(b[j][0]), "r"(b[j][1]));
        }
    }
#pragma unroll
    for (int i = 0; i < 2; i++) {
        int row = m0 + wm0 + i*16 + gid;
#pragma unroll
        for (int j = 0; j < 8; j++) {
            int col = n0 + wn0 + j*8 + tig*2;
            *(float2*)(C + (size_t)row*Ng + col)     = make_float2(acc[i][j][0], acc[i][j][1]);
            *(float2*)(C + (size_t)(row+8)*Ng + col) = make_float2(acc[i][j][2], acc[i][j][3]);
        }
    }
}

// ---------------- per-sequence fused middle ----------------
// smem layout (floats)
#define S_XM  0        // [16][256] x_m
#define S_XC  4096     // [16][256]
#define S_QT  8192     // q transposed: [i][t], stride 17
#define S_K   12544    // [t][266]
#define S_V   16800    // [t][266]
#define S_HT  21056    // hs transposed: [i][s], stride 17
#define S_IG  25408
#define S_FG  25472
#define S_LFC 25536    // [h][17]
#define S_AA  25604    // [h][16]
#define S_WM  25668    // [h][s][t]
#define SM3_FLOATS 26692

__global__ void __launch_bounds__(256,2) k_seq(
    const float* __restrict__ UP,
    const float* __restrict__ conv_w, const float* __restrict__ conv_b,
    const float* __restrict__ Wq, const float* __restrict__ Wk, const float* __restrict__ Wv,
    const float* __restrict__ ig_w, const float* __restrict__ ig_b,
    const float* __restrict__ fg_w, const float* __restrict__ fg_b,
    const float* __restrict__ ln_w, const float* __restrict__ skip,
    float* __restrict__ HS) {
    extern __shared__ float sm[];
    const int tid = threadIdx.x;
    const int seq = blockIdx.x;

    // --- load x_m [16][256] (first half of UP rows) ---
    {
        const float4* src = (const float4*)(UP + (size_t)seq * 16 * 512);
        float4* d4 = (float4*)(sm + S_XM);
        for (int i = tid; i < 1024; i += 256) {
            int row = i >> 6, q = i & 63;
            d4[row*64 + q] = src[row*128 + q];
        }
    }
    __syncthreads();

    // --- causal depthwise conv (K=4) + silu -> xc ---
    for (int e = tid; e < 4096; e += 256) {
        int t = e >> 8, i = e & 255;
        float a = conv_b[i];
#pragma unroll
        for (int j = 0; j < 4; j++) {
            int tt = t + j - 3;
            if (tt >= 0) a += conv_w[j*256 + i] * sm[S_XM + tt*256 + i];
        }
        sm[S_XC + t*256 + i] = siluf(a);
    }
    __syncthreads();

    // --- block-diagonal q,k,v (4x4 blocks) ---
    for (int e = tid; e < 4096; e += 256) {
        int t = e >> 8, col = e & 255;
        int n = col >> 2, o = col & 3;
        const float* wq = Wq + n*16 + o*4;
        const float* wk = Wk + n*16 + o*4;
        const float* wv = Wv + n*16 + o*4;
        float aq = 0.f, ak = 0.f, av = 0.f;
#pragma unroll
        for (int i2 = 0; i2 < 4; i2++) {
            float xcv = sm[S_XC + t*256 + n*4 + i2];
            float xmv = sm[S_XM + t*256 + n*4 + i2];
            aq += xcv * wq[i2];
            ak += xcv * wk[i2];
            av += xmv * wv[i2];
        }
        sm[S_QT + col*17 + t]  = aq;
        sm[S_K  + t*266 + col] = ak;
        sm[S_V  + t*266 + col] = av;
    }
    __syncthreads();

    // --- gate preacts ig/fg ---
    {
        int half = tid & 1, gh = (tid >> 1) & 3, gt = (tid >> 3) & 15, gate = (tid >> 7) & 1;
        const float* gw = gate ? fg_w : ig_w;
        float a = 0.f;
        int j0 = half * 384;
        for (int jj = j0; jj < j0 + 384; jj++) {
            float v;
            if (jj < 256)      v = sm[S_QT + jj*17 + gt];
            else if (jj < 512) v = sm[S_K + gt*266 + (jj - 256)];
            else               v = sm[S_V + gt*266 + (jj - 512)];
            a += v * gw[jj*4 + gh];
        }
        a += __shfl_xor_sync(0xffffffffu, a, 1);
        if (half == 0) {
            float bias = gate ? fg_b[gh] : ig_b[gh];
            sm[(gate ? S_FG : S_IG) + gt*4 + gh] = a + bias;
        }
    }
    __syncthreads();

    // --- per-head cumulative log-forget ---
    if (tid < 4) {
        int hh2 = tid;
        float cum = 0.f;
        sm[S_LFC + hh2*17 + 0] = 0.f;
        for (int t = 0; t < 16; t++) {
            cum += lsig(sm[S_FG + t*4 + hh2]);
            sm[S_LFC + hh2*17 + t + 1] = cum;
            sm[S_AA + hh2*16 + t] = sm[S_IG + t*4 + hh2] - cum;
        }
    }

    // --- qk ---
    const int mh = tid >> 6;
    const int ms = (tid >> 2) & 15;
    const int mtq = tid & 3;
    float qk0 = 0.f, qk1 = 0.f, qk2 = 0.f, qk3 = 0.f;
    {
        int qtb = mh*64*17 + ms;
        int kb = (mtq*4)*266 + mh*64;
#pragma unroll 4
        for (int d = 0; d < 64; d++) {
            float qv = sm[S_QT + qtb + d*17];
            qk0 += qv * sm[S_K + kb +       d];
            qk1 += qv * sm[S_K + kb + 266 + d];
            qk2 += qv * sm[S_K + kb + 532 + d];
            qk3 += qv * sm[S_K + kb + 798 + d];
        }
    }
    __syncthreads();

    // --- D-weights + normalizer -> wm ---
    {
        float qks[4] = {qk0*0.125f, qk1*0.125f, qk2*0.125f, qk3*0.125f};
        float cs = sm[S_LFC + mh*17 + ms + 1];
        float mloc = -1e30f;
        float ldv[4];
#pragma unroll
        for (int j = 0; j < 4; j++) {
            int t = mtq*4 + j;
            if (t <= ms) { ldv[j] = cs + sm[S_AA + mh*16 + t]; mloc = fmaxf(mloc, ldv[j]); }
            else ldv[j] = 0.f;
        }
        mloc = fmaxf(mloc, __shfl_xor_sync(0xffffffffu, mloc, 1));
        mloc = fmaxf(mloc, __shfl_xor_sync(0xffffffffu, mloc, 2));
        float cv[4]; float csum = 0.f;
#pragma unroll
        for (int j = 0; j < 4; j++) {
            int t = mtq*4 + j;
            cv[j] = (t <= ms) ? qks[j] * expf(ldv[j] - mloc) : 0.f;
            csum += cv[j];
        }
        csum += __shfl_xor_sync(0xffffffffu, csum, 1);
        csum += __shfl_xor_sync(0xffffffffu, csum, 2);
        float norm = fmaxf(fabsf(csum), expf(-mloc)) + 1e-6f;
        float inv = 1.f / norm;
#pragma unroll
        for (int j = 0; j < 4; j++)
            sm[S_WM + (mh*16 + ms)*16 + mtq*4 + j] = cv[j] * inv;
    }
    __syncthreads();

    // --- out = wm @ v ---
    {
        int hC = tid >> 6, dC = tid & 63;
        float vreg[16];
#pragma unroll
        for (int t = 0; t < 16; t++) vreg[t] = sm[S_V + t*266 + hC*64 + dC];
#pragma unroll
        for (int s2 = 0; s2 < 16; s2++) {
            float a2 = 0.f;
#pragma unroll
            for (int t = 0; t < 16; t++)
                a2 += sm[S_WM + (hC*16 + s2)*16 + t] * vreg[t];
            sm[S_HT + (hC*64 + dC)*17 + s2] = a2;
        }
    }
    __syncthreads();

    // --- group LayerNorm + skip*xc + silu(z) gate (z read from global) ---
    {
        int hD = tid >> 6, sD = (tid >> 2) & 15, dq = tid & 3;
        float vals[16]; float sum = 0.f, sq = 0.f;
#pragma unroll
        for (int dd = 0; dd < 16; dd++) {
            int i = hD*64 + dq*16 + dd;
            float v = sm[S_HT + i*17 + sD];
            vals[dd] = v; sum += v; sq += v*v;
        }
        sum += __shfl_xor_sync(0xffffffffu, sum, 1);
        sum += __shfl_xor_sync(0xffffffffu, sum, 2);
        sq  += __shfl_xor_sync(0xffffffffu, sq, 1);
        sq  += __shfl_xor_sync(0xffffffffu, sq, 2);
        float mu = sum * (1.f/64.f);
        float var = sq * (1.f/64.f) - mu*mu;
        float rstd = rsqrtf(var + 1e-5f);
        const float* zrow = UP + (size_t)seq*8192 + sD*512 + 256;
#pragma unroll
        for (int dd = 0; dd < 16; dd++) {
            int i = hD*64 + dq*16 + dd;
            float hn = (vals[dd] - mu) * rstd * ln_w[i];
            float zz = zrow[i];
            float o = (hn + skip[i] * sm[S_XC + sD*256 + i]) * siluf(zz);
            sm[S_HT + i*17 + sD] = o;
        }
    }
    __syncthreads();

    // --- coalesced write HS[row][i] ---
    {
        float* dst = HS + (size_t)seq * 16 * 256;
        for (int idx = tid; idx < 4096; idx += 256) {
            int t = idx >> 8, i = idx & 255;
            dst[idx] = sm[S_HT + i*17 + t];
        }
    }
}

// ---------------- launch ----------------
extern "C" void kernel_launch(void* const* d_in, const int* in_sizes, int n_in,
                              void* d_out, int out_size) {
    const float* x      = (const float*)d_in[0];
    const float* W_up   = (const float*)d_in[1];
    const float* conv_w = (const float*)d_in[2];
    const float* conv_b = (const float*)d_in[3];
    const float* Wq     = (const float*)d_in[4];
    const float* Wk     = (const float*)d_in[5];
    const float* Wv     = (const float*)d_in[6];
    const float* ig_w   = (const float*)d_in[7];
    const float* ig_b   = (const float*)d_in[8];
    const float* fg_w   = (const float*)d_in[9];
    const float* fg_b   = (const float*)d_in[10];
    const float* ln_w   = (const float*)d_in[11];
    const float* skip   = (const float*)d_in[12];
    const float* W_down = (const float*)d_in[13];
    float* out = (float*)d_out;

    float *XS, *UP, *HS, *OT, *WTU, *WTD;
    cudaGetSymbolAddress((void**)&XS,  g_XS);
    cudaGetSymbolAddress((void**)&UP,  g_UP);
    cudaGetSymbolAddress((void**)&HS,  g_HS);
    cudaGetSymbolAddress((void**)&OT,  g_OT);
    cudaGetSymbolAddress((void**)&WTU, g_WTU);
    cudaGetSymbolAddress((void**)&WTD, g_WTD);

    cudaFuncSetAttribute(k_seq, cudaFuncAttributeMaxDynamicSharedMemorySize,
                         SM3_FLOATS * (int)sizeof(float));

    k_transpose_in<<<4096, 256>>>(x, XS);
    k_wt<<<256, 256>>>(W_up, WTU, 128, 512);
    k_wt<<<128, 256>>>(W_down, WTD, 256, 128);
    // up: C[131072,512] = XS[131072,128] @ WTU[512,128]^T
    k_gemm_mma<<<dim3(4, 1024), 256>>>(XS, WTU, UP, 512, 128);
    k_seq<<<SEQS, 256, SM3_FLOATS * sizeof(float)>>>(UP, conv_w, conv_b,
        Wq, Wk, Wv, ig_w, ig_b, fg_w, fg_b, ln_w, skip, HS);
    // down: C[131072,128] = HS[131072,256] @ WTD[128,256]^T
    k_gemm_mma<<<dim3(1, 1024), 256>>>(HS, WTD, OT, 128, 256);
    k_transpose_out<<<4096, 256>>>(OT, out);
}

// round 5
// speedup vs baseline: 2.5164x; 1.4108x over previous
#include <cuda_runtime.h>
#include <cstdint>
#include <math.h>

// ---------------- problem constants ----------------
#define DIMC  128
#define TT    16
#define INNER 256
#define SEQS  8192
#define ROWS  (SEQS*TT)         // 131072
#define UPCOLS 512

// ---------------- scratch (static device, no allocs) ----------------
__device__ float g_XS[(size_t)ROWS*DIMC];    // [row][128]
__device__ float g_UP[(size_t)ROWS*UPCOLS];  // [row][512]
__device__ float g_HS[(size_t)ROWS*INNER];   // [row][256]
__device__ float g_OT[(size_t)ROWS*DIMC];    // [row][128]
__device__ float g_WTU[512*128];             // W_up^T  [n][k]
__device__ float g_WTD[128*256];             // W_down^T [n][k]

// ---------------- helpers ----------------
__device__ __forceinline__ float siluf(float x){ return x / (1.f + __expf(-x)); }
__device__ __forceinline__ float lsig(float x){ return fminf(x,0.f) - log1pf(expf(-fabsf(x))); }
__device__ __forceinline__ uint32_t f2tf32(float f){
    uint32_t o; asm("cvt.rna.tf32.f32 %0, %1;" : "=r"(o) : "f"(f)); return o;
}

// ---------------- kernel: (b,c,t,h,w) -> XS[seq][t][c] ----------------
__global__ void __launch_bounds__(256) k_transpose_in(const float* __restrict__ x,
                                                      float* __restrict__ XS) {
    __shared__ float tile[128*33];
    int bid = blockIdx.x;
    int b = bid >> 9;
    int t = (bid >> 5) & 15;
    int h = bid & 31;
    const float* src = x + ((size_t)(b*128)*16 + t) * 1024 + h*32;
    for (int idx = threadIdx.x; idx < 128*32; idx += 256) {
        int c = idx >> 5, w = idx & 31;
        tile[c*33 + w] = src[(size_t)c*16384 + w];
    }
    __syncthreads();
    size_t base = ((size_t)(b*1024 + h*32) * 16 + t) * 128;
    for (int idx = threadIdx.x; idx < 32*128; idx += 256) {
        int w = idx >> 7, c = idx & 127;
        XS[base + (size_t)w*2048 + c] = tile[c*33 + w];
    }
}

// ---------------- kernel: OT[row][c] -> out (b,c,t,h,w) ----------------
__global__ void __launch_bounds__(256) k_transpose_out(const float* __restrict__ OT,
                                                       float* __restrict__ out) {
    __shared__ float tile[128*33];
    int bid = blockIdx.x;
    int b = bid >> 9;
    int t = (bid >> 5) & 15;
    int h = bid & 31;
    size_t base = ((size_t)(b*1024 + h*32) * 16 + t) * 128;
    for (int idx = threadIdx.x; idx < 32*128; idx += 256) {
        int w = idx >> 7, c = idx & 127;
        tile[c*33 + w] = OT[base + (size_t)w*2048 + c];
    }
    __syncthreads();
    float* dst = out + ((size_t)(b*128)*16 + t) * 1024 + h*32;
    for (int idx = threadIdx.x; idx < 128*32; idx += 256) {
        int c = idx >> 5, w = idx & 31;
        dst[(size_t)c*16384 + w] = tile[c*33 + w];
    }
}

// ---------------- weight transpose: Wt[n][k] = W[k][n] ----------------
__global__ void k_wt(const float* __restrict__ W, float* __restrict__ Wt, int K, int N){
    int idx = blockIdx.x*256 + threadIdx.x;
    if (idx < K*N) { int k = idx / N, n = idx - k*N; Wt[(size_t)n*K + k] = W[idx]; }
}

// ---------------- TF32 warp-MMA GEMM: C[M,Ng] = A[M,K] @ Bt[Ng,K]^T ----------------
__global__ void __launch_bounds__(256) k_gemm_mma(const float* __restrict__ A,
        const float* __restrict__ Bt, float* __restrict__ C, int Ng, int Kf) {
    __shared__ uint32_t As[128*36];
    __shared__ uint32_t Bs[128*36];
    const int tid  = threadIdx.x;
    const int lane = tid & 31, warp = tid >> 5;
    const int gid  = lane >> 2, tig = lane & 3;
    const int wm0  = (warp >> 1) * 32;
    const int wn0  = (warp & 1) * 64;
    const int m0 = blockIdx.y * 128, n0 = blockIdx.x * 128;

    float acc[2][8][4];
#pragma unroll
    for (int i = 0; i < 2; i++)
#pragma unroll
        for (int j = 0; j < 8; j++)
#pragma unroll
            for (int e = 0; e < 4; e++) acc[i][j][e] = 0.f;

    for (int kb = 0; kb < Kf; kb += 32) {
        __syncthreads();
#pragma unroll
        for (int r = 0; r < 4; r++) {
            int f = tid + 256*r;
            int row = f >> 3, q = (f & 7) << 2;
            float4 va = *(const float4*)(A  + (size_t)(m0+row)*Kf + kb + q);
            float4 vb = *(const float4*)(Bt + (size_t)(n0+row)*Kf + kb + q);
            uint32_t* pa = &As[row*36 + q];
            uint32_t* pb = &Bs[row*36 + q];
            pa[0] = f2tf32(va.x); pa[1] = f2tf32(va.y);
            pa[2] = f2tf32(va.z); pa[3] = f2tf32(va.w);
            pb[0] = f2tf32(vb.x); pb[1] = f2tf32(vb.y);
            pb[2] = f2tf32(vb.z); pb[3] = f2tf32(vb.w);
        }
        __syncthreads();
#pragma unroll
        for (int ks = 0; ks < 4; ks++) {
            const int k = ks*8;
            uint32_t a[2][4], b[8][2];
#pragma unroll
            for (int i = 0; i < 2; i++) {
                int r = wm0 + i*16 + gid;
                a[i][0] = As[r*36 + k + tig];
                a[i][1] = As[(r+8)*36 + k + tig];
                a[i][2] = As[r*36 + k + tig + 4];
                a[i][3] = As[(r+8)*36 + k + tig + 4];
            }
#pragma unroll
            for (int j = 0; j < 8; j++) {
                int r = wn0 + j*8 + gid;
                b[j][0] = Bs[r*36 + k + tig];
                b[j][1] = Bs[r*36 + k + tig + 4];
            }
#pragma unroll
            for (int i = 0; i < 2; i++)
#pragma unroll
                for (int j = 0; j < 8; j++)
                    asm volatile(
                        "mma.sync.aligned.m16n8k8.row.col.f32.tf32.tf32.f32 "
                        "{%0,%1,%2,%3}, {%4,%5,%6,%7}, {%8,%9}, {%0,%1,%2,%3};"
                        : "+f"(acc[i][j][0]), "+f"(acc[i][j][1]),
                          "+f"(acc[i][j][2]), "+f"(acc[i][j][3])
                        : "r"(a[i][0]), "r"(a[i][1]), "r"(a[i][2]), "r"(a[i][3]),
                          "r"(b[j][0]), "r"(b[j][1]));
        }
    }
#pragma unroll
    for (int i = 0; i < 2; i++) {
        int row = m0 + wm0 + i*16 + gid;
#pragma unroll
        for (int j = 0; j < 8; j++) {
            int col = n0 + wn0 + j*8 + tig*2;
            *(float2*)(C + (size_t)row*Ng + col)     = make_float2(acc[i][j][0], acc[i][j][1]);
            *(float2*)(C + (size_t)(row+8)*Ng + col) = make_float2(acc[i][j][2], acc[i][j][3]);
        }
    }
}

// ---------------- per-sequence fused middle ----------------
// smem layout (floats)
#define S_XM  0        // [16][256] x_m
#define S_XC  4096     // [16][256]
#define S_QT  8192     // q transposed: [i][t], stride 17
#define S_K   12544    // [t][266]
#define S_V   16800    // [t][266]
#define S_HT  21056    // hs transposed: [i][s], stride 17
#define S_IG  25408
#define S_FG  25472
#define S_LFC 25536    // [h][17]
#define S_AA  25604    // [h][16]
#define S_WM  25668    // [h][s][t]
#define SM3_FLOATS 26692

__global__ void __launch_bounds__(256,2) k_seq(
    const float* __restrict__ UP,
    const float* __restrict__ conv_w, const float* __restrict__ conv_b,
    const float* __restrict__ Wq, const float* __restrict__ Wk, const float* __restrict__ Wv,
    const float* __restrict__ ig_w, const float* __restrict__ ig_b,
    const float* __restrict__ fg_w, const float* __restrict__ fg_b,
    const float* __restrict__ ln_w, const float* __restrict__ skip,
    float* __restrict__ HS) {
    extern __shared__ float sm[];
    const int tid = threadIdx.x;
    const int seq = blockIdx.x;

    // --- load x_m [16][256] (first half of UP rows) ---
    {
        const float4* src = (const float4*)(UP + (size_t)seq * 16 * 512);
        float4* d4 = (float4*)(sm + S_XM);
        for (int i = tid; i < 1024; i += 256) {
            int row = i >> 6, q = i & 63;
            d4[row*64 + q] = src[row*128 + q];
        }
    }
    __syncthreads();

    // --- causal depthwise conv (K=4) + silu -> xc ---
    for (int e = tid; e < 4096; e += 256) {
        int t = e >> 8, i = e & 255;
        float a = conv_b[i];
#pragma unroll
        for (int j = 0; j < 4; j++) {
            int tt = t + j - 3;
            if (tt >= 0) a += conv_w[j*256 + i] * sm[S_XM + tt*256 + i];
        }
        sm[S_XC + t*256 + i] = siluf(a);
    }
    __syncthreads();

    // --- block-diagonal q,k,v (4x4 blocks, float4 dot products) ---
    for (int e = tid; e < 4096; e += 256) {
        int t = e >> 8, col = e & 255;
        int n = col >> 2, o = col & 3;
        float4 wq4 = *(const float4*)(Wq + n*16 + o*4);
        float4 wk4 = *(const float4*)(Wk + n*16 + o*4);
        float4 wv4 = *(const float4*)(Wv + n*16 + o*4);
        float4 xc4 = *(const float4*)&sm[S_XC + t*256 + n*4];
        float4 xm4 = *(const float4*)&sm[S_XM + t*256 + n*4];
        float aq = xc4.x*wq4.x + xc4.y*wq4.y + xc4.z*wq4.z + xc4.w*wq4.w;
        float ak = xc4.x*wk4.x + xc4.y*wk4.y + xc4.z*wk4.z + xc4.w*wk4.w;
        float av = xm4.x*wv4.x + xm4.y*wv4.y + xm4.z*wv4.z + xm4.w*wv4.w;
        sm[S_QT + col*17 + t]  = aq;
        sm[S_K  + t*266 + col] = ak;
        sm[S_V  + t*266 + col] = av;
    }
    __syncthreads();

    // --- gate preacts ig/fg: thread (t, c) covers j = i*16 + c, all 8 outputs ---
    {
        const int gt = tid >> 4;       // t  (0..15)
        const int gc = tid & 15;       // chunk lane (0..15)
        float accI[4] = {0.f,0.f,0.f,0.f};
        float accF[4] = {0.f,0.f,0.f,0.f};
        // segment 0: q from QT (stride 17)
#pragma unroll
        for (int i = 0; i < 16; i++) {
            int jj = i*16 + gc;
            float v = sm[S_QT + jj*17 + gt];
            float4 wi = *(const float4*)(ig_w + jj*4);
            float4 wf = *(const float4*)(fg_w + jj*4);
            accI[0] += v*wi.x; accI[1] += v*wi.y; accI[2] += v*wi.z; accI[3] += v*wi.w;
            accF[0] += v*wf.x; accF[1] += v*wf.y; accF[2] += v*wf.z; accF[3] += v*wf.w;
        }
        // segment 1: k
#pragma unroll
        for (int i = 0; i < 16; i++) {
            int jj = 256 + i*16 + gc;
            float v = sm[S_K + gt*266 + (i*16 + gc)];
            float4 wi = *(const float4*)(ig_w + jj*4);
            float4 wf = *(const float4*)(fg_w + jj*4);
            accI[0] += v*wi.x; accI[1] += v*wi.y; accI[2] += v*wi.z; accI[3] += v*wi.w;
            accF[0] += v*wf.x; accF[1] += v*wf.y; accF[2] += v*wf.z; accF[3] += v*wf.w;
        }
        // segment 2: v
#pragma unroll
        for (int i = 0; i < 16; i++) {
            int jj = 512 + i*16 + gc;
            float v = sm[S_V + gt*266 + (i*16 + gc)];
            float4 wi = *(const float4*)(ig_w + jj*4);
            float4 wf = *(const float4*)(fg_w + jj*4);
            accI[0] += v*wi.x; accI[1] += v*wi.y; accI[2] += v*wi.z; accI[3] += v*wi.w;
            accF[0] += v*wf.x; accF[1] += v*wf.y; accF[2] += v*wf.z; accF[3] += v*wf.w;
        }
        // reduce over the 16 chunk lanes (stays within each 16-lane half)
#pragma unroll
        for (int m = 1; m < 16; m <<= 1) {
#pragma unroll
            for (int g = 0; g < 4; g++) {
                accI[g] += __shfl_xor_sync(0xffffffffu, accI[g], m);
                accF[g] += __shfl_xor_sync(0xffffffffu, accF[g], m);
            }
        }
        if (gc == 0) {
#pragma unroll
            for (int g = 0; g < 4; g++) {
                sm[S_IG + gt*4 + g] = accI[g] + ig_b[g];
                sm[S_FG + gt*4 + g] = accF[g] + fg_b[g];
            }
        }
    }
    __syncthreads();

    // --- per-head cumulative log-forget ---
    if (tid < 4) {
        int hh2 = tid;
        float cum = 0.f;
        sm[S_LFC + hh2*17 + 0] = 0.f;
        for (int t = 0; t < 16; t++) {
            cum += lsig(sm[S_FG + t*4 + hh2]);
            sm[S_LFC + hh2*17 + t + 1] = cum;
            sm[S_AA + hh2*16 + t] = sm[S_IG + t*4 + hh2] - cum;
        }
    }

    // --- qk ---
    const int mh = tid >> 6;
    const int ms = (tid >> 2) & 15;
    const int mtq = tid & 3;
    float qk0 = 0.f, qk1 = 0.f, qk2 = 0.f, qk3 = 0.f;
    {
        int qtb = mh*64*17 + ms;
        int kb = (mtq*4)*266 + mh*64;
#pragma unroll 4
        for (int d = 0; d < 64; d++) {
            float qv = sm[S_QT + qtb + d*17];
            qk0 += qv * sm[S_K + kb +       d];
            qk1 += qv * sm[S_K + kb + 266 + d];
            qk2 += qv * sm[S_K + kb + 532 + d];
            qk3 += qv * sm[S_K + kb + 798 + d];
        }
    }
    __syncthreads();

    // --- D-weights + normalizer -> wm ---
    {
        float qks[4] = {qk0*0.125f, qk1*0.125f, qk2*0.125f, qk3*0.125f};
        float cs = sm[S_LFC + mh*17 + ms + 1];
        float mloc = -1e30f;
        float ldv[4];
#pragma unroll
        for (int j = 0; j < 4; j++) {
            int t = mtq*4 + j;
            if (t <= ms) { ldv[j] = cs + sm[S_AA + mh*16 + t]; mloc = fmaxf(mloc, ldv[j]); }
            else ldv[j] = 0.f;
        }
        mloc = fmaxf(mloc, __shfl_xor_sync(0xffffffffu, mloc, 1));
        mloc = fmaxf(mloc, __shfl_xor_sync(0xffffffffu, mloc, 2));
        float cv[4]; float csum = 0.f;
#pragma unroll
        for (int j = 0; j < 4; j++) {
            int t = mtq*4 + j;
            cv[j] = (t <= ms) ? qks[j] * __expf(ldv[j] - mloc) : 0.f;
            csum += cv[j];
        }
        csum += __shfl_xor_sync(0xffffffffu, csum, 1);
        csum += __shfl_xor_sync(0xffffffffu, csum, 2);
        float norm = fmaxf(fabsf(csum), __expf(-mloc)) + 1e-6f;
        float inv = 1.f / norm;
#pragma unroll
        for (int j = 0; j < 4; j++)
            sm[S_WM + (mh*16 + ms)*16 + mtq*4 + j] = cv[j] * inv;
    }
    __syncthreads();

    // --- out = wm @ v ---
    {
        int hC = tid >> 6, dC = tid & 63;
        float vreg[16];
#pragma unroll
        for (int t = 0; t < 16; t++) vreg[t] = sm[S_V + t*266 + hC*64 + dC];
#pragma unroll
        for (int s2 = 0; s2 < 16; s2++) {
            float a2 = 0.f;
#pragma unroll
            for (int t = 0; t < 16; t++)
                a2 += sm[S_WM + (hC*16 + s2)*16 + t] * vreg[t];
            sm[S_HT + (hC*64 + dC)*17 + s2] = a2;
        }
    }
    __syncthreads();

    // --- group LayerNorm + skip*xc + silu(z) gate (z read from global) ---
    {
        int hD = tid >> 6, sD = (tid >> 2) & 15, dq = tid & 3;
        float vals[16]; float sum = 0.f, sq = 0.f;
#pragma unroll
        for (int dd = 0; dd < 16; dd++) {
            int i = hD*64 + dq*16 + dd;
            float v = sm[S_HT + i*17 + sD];
            vals[dd] = v; sum += v; sq += v*v;
        }
        sum += __shfl_xor_sync(0xffffffffu, sum, 1);
        sum += __shfl_xor_sync(0xffffffffu, sum, 2);
        sq  += __shfl_xor_sync(0xffffffffu, sq, 1);
        sq  += __shfl_xor_sync(0xffffffffu, sq, 2);
        float mu = sum * (1.f/64.f);
        float var = sq * (1.f/64.f) - mu*mu;
        float rstd = rsqrtf(var + 1e-5f);
        const float* zrow = UP + (size_t)seq*8192 + sD*512 + 256;
#pragma unroll
        for (int dd = 0; dd < 16; dd++) {
            int i = hD*64 + dq*16 + dd;
            float hn = (vals[dd] - mu) * rstd * ln_w[i];
            float zz = zrow[i];
            float o = (hn + skip[i] * sm[S_XC + sD*256 + i]) * siluf(zz);
            sm[S_HT + i*17 + sD] = o;
        }
    }
    __syncthreads();

    // --- coalesced write HS[row][i] ---
    {
        float* dst = HS + (size_t)seq * 16 * 256;
        for (int idx = tid; idx < 4096; idx += 256) {
            int t = idx >> 8, i = idx & 255;
            dst[idx] = sm[S_HT + i*17 + t];
        }
    }
}

// ---------------- launch ----------------
extern "C" void kernel_launch(void* const* d_in, const int* in_sizes, int n_in,
                              void* d_out, int out_size) {
    const float* x      = (const float*)d_in[0];
    const float* W_up   = (const float*)d_in[1];
    const float* conv_w = (const float*)d_in[2];
    const float* conv_b = (const float*)d_in[3];
    const float* Wq     = (const float*)d_in[4];
    const float* Wk     = (const float*)d_in[5];
    const float* Wv     = (const float*)d_in[6];
    const float* ig_w   = (const float*)d_in[7];
    const float* ig_b   = (const float*)d_in[8];
    const float* fg_w   = (const float*)d_in[9];
    const float* fg_b   = (const float*)d_in[10];
    const float* ln_w   = (const float*)d_in[11];
    const float* skip   = (const float*)d_in[12];
    const float* W_down = (const float*)d_in[13];
    float* out = (float*)d_out;

    float *XS, *UP, *HS, *OT, *WTU, *WTD;
    cudaGetSymbolAddress((void**)&XS,  g_XS);
    cudaGetSymbolAddress((void**)&UP,  g_UP);
    cudaGetSymbolAddress((void**)&HS,  g_HS);
    cudaGetSymbolAddress((void**)&OT,  g_OT);
    cudaGetSymbolAddress((void**)&WTU, g_WTU);
    cudaGetSymbolAddress((void**)&WTD, g_WTD);

    cudaFuncSetAttribute(k_seq, cudaFuncAttributeMaxDynamicSharedMemorySize,
                         SM3_FLOATS * (int)sizeof(float));

    k_transpose_in<<<4096, 256>>>(x, XS);
    k_wt<<<256, 256>>>(W_up, WTU, 128, 512);
    k_wt<<<128, 256>>>(W_down, WTD, 256, 128);
    // up: C[131072,512] = XS[131072,128] @ WTU[512,128]^T
    k_gemm_mma<<<dim3(4, 1024), 256>>>(XS, WTU, UP, 512, 128);
    k_seq<<<SEQS, 256, SM3_FLOATS * sizeof(float)>>>(UP, conv_w, conv_b,
        Wq, Wk, Wv, ig_w, ig_b, fg_w, fg_b, ln_w, skip, HS);
    // down: C[131072,128] = HS[131072,256] @ WTD[128,256]^T
    k_gemm_mma<<<dim3(1, 1024), 256>>>(HS, WTD, OT, 128, 256);
    k_transpose_out<<<4096, 256>>>(OT, out);
}

// round 6
// speedup vs baseline: 2.9115x; 1.1570x over previous
#include <cuda_runtime.h>
#include <cuda_fp16.h>
#include <cstdint>
#include <math.h>

// ---------------- problem constants ----------------
#define DIMC  128
#define TT    16
#define INNER 256
#define SEQS  8192
#define ROWS  (SEQS*TT)         // 131072
#define UPCOLS 512

// ---------------- scratch (static device, no allocs) ----------------
__device__ float g_XS[(size_t)ROWS*DIMC];    // [row][128]
__device__ float g_UP[(size_t)ROWS*UPCOLS];  // [row][512]
__device__ float g_HS[(size_t)ROWS*INNER];   // [row][256]
__device__ float g_OT[(size_t)ROWS*DIMC];    // [row][128]
__device__ float g_WTU[512*128];             // W_up^T  [n][k]
__device__ float g_WTD[128*256];             // W_down^T [n][k]

// ---------------- helpers ----------------
__device__ __forceinline__ float siluf(float x){ return x / (1.f + __expf(-x)); }
__device__ __forceinline__ uint32_t f2tf32(float f){
    uint32_t o; asm("cvt.rna.tf32.f32 %0, %1;" : "=r"(o) : "f"(f)); return o;
}

// ---------------- kernel: (b,c,t,h,w) -> XS[seq][t][c] ----------------
__global__ void __launch_bounds__(256) k_transpose_in(const float* __restrict__ x,
                                                      float* __restrict__ XS) {
    __shared__ float tile[128*33];
    int bid = blockIdx.x;
    int b = bid >> 9;
    int t = (bid >> 5) & 15;
    int h = bid & 31;
    const float* src = x + ((size_t)(b*128)*16 + t) * 1024 + h*32;
    for (int idx = threadIdx.x; idx < 128*32; idx += 256) {
        int c = idx >> 5, w = idx & 31;
        tile[c*33 + w] = src[(size_t)c*16384 + w];
    }
    __syncthreads();
    size_t base = ((size_t)(b*1024 + h*32) * 16 + t) * 128;
    for (int idx = threadIdx.x; idx < 32*128; idx += 256) {
        int w = idx >> 7, c = idx & 127;
        XS[base + (size_t)w*2048 + c] = tile[c*33 + w];
    }
}

// ---------------- kernel: OT[row][c] -> out (b,c,t,h,w) ----------------
__global__ void __launch_bounds__(256) k_transpose_out(const float* __restrict__ OT,
                                                       float* __restrict__ out) {
    __shared__ float tile[128*33];
    int bid = blockIdx.x;
    int b = bid >> 9;
    int t = (bid >> 5) & 15;
    int h = bid & 31;
    size_t base = ((size_t)(b*1024 + h*32) * 16 + t) * 128;
    for (int idx = threadIdx.x; idx < 32*128; idx += 256) {
        int w = idx >> 7, c = idx & 127;
        tile[c*33 + w] = OT[base + (size_t)w*2048 + c];
    }
    __syncthreads();
    float* dst = out + ((size_t)(b*128)*16 + t) * 1024 + h*32;
    for (int idx = threadIdx.x; idx < 128*32; idx += 256) {
        int c = idx >> 5, w = idx & 31;
        dst[(size_t)c*16384 + w] = tile[c*33 + w];
    }
}

// ---------------- weight transpose: Wt[n][k] = W[k][n] ----------------
__global__ void k_wt(const float* __restrict__ W, float* __restrict__ Wt, int K, int N){
    int idx = blockIdx.x*256 + threadIdx.x;
    if (idx < K*N) { int k = idx / N, n = idx - k*N; Wt[(size_t)n*K + k] = W[idx]; }
}

// ---------------- TF32 warp-MMA GEMM: C[M,Ng] = A[M,K] @ Bt[Ng,K]^T ----------------
__global__ void __launch_bounds__(256) k_gemm_mma(const float* __restrict__ A,
        const float* __restrict__ Bt, float* __restrict__ C, int Ng, int Kf) {
    __shared__ uint32_t As[128*36];
    __shared__ uint32_t Bs[128*36];
    const int tid  = threadIdx.x;
    const int lane = tid & 31, warp = tid >> 5;
    const int gid  = lane >> 2, tig = lane & 3;
    const int wm0  = (warp >> 1) * 32;
    const int wn0  = (warp & 1) * 64;
    const int m0 = blockIdx.y * 128, n0 = blockIdx.x * 128;

    float acc[2][8][4];
#pragma unroll
    for (int i = 0; i < 2; i++)
#pragma unroll
        for (int j = 0; j < 8; j++)
#pragma unroll
            for (int e = 0; e < 4; e++) acc[i][j][e] = 0.f;

    for (int kb = 0; kb < Kf; kb += 32) {
        __syncthreads();
#pragma unroll
        for (int r = 0; r < 4; r++) {
            int f = tid + 256*r;
            int row = f >> 3, q = (f & 7) << 2;
            float4 va = *(const float4*)(A  + (size_t)(m0+row)*Kf + kb + q);
            float4 vb = *(const float4*)(Bt + (size_t)(n0+row)*Kf + kb + q);
            uint32_t* pa = &As[row*36 + q];
            uint32_t* pb = &Bs[row*36 + q];
            pa[0] = f2tf32(va.x); pa[1] = f2tf32(va.y);
            pa[2] = f2tf32(va.z); pa[3] = f2tf32(va.w);
            pb[0] = f2tf32(vb.x); pb[1] = f2tf32(vb.y);
            pb[2] = f2tf32(vb.z); pb[3] = f2tf32(vb.w);
        }
        __syncthreads();
#pragma unroll
        for (int ks = 0; ks < 4; ks++) {
            const int k = ks*8;
            uint32_t a[2][4], b[8][2];
#pragma unroll
            for (int i = 0; i < 2; i++) {
                int r = wm0 + i*16 + gid;
                a[i][0] = As[r*36 + k + tig];
                a[i][1] = As[(r+8)*36 + k + tig];
                a[i][2] = As[r*36 + k + tig + 4];
                a[i][3] = As[(r+8)*36 + k + tig + 4];
            }
#pragma unroll
            for (int j = 0; j < 8; j++) {
                int r = wn0 + j*8 + gid;
                b[j][0] = Bs[r*36 + k + tig];
                b[j][1] = Bs[r*36 + k + tig + 4];
            }
#pragma unroll
            for (int i = 0; i < 2; i++)
#pragma unroll
                for (int j = 0; j < 8; j++)
                    asm volatile(
                        "mma.sync.aligned.m16n8k8.row.col.f32.tf32.tf32.f32 "
                        "{%0,%1,%2,%3}, {%4,%5,%6,%7}, {%8,%9}, {%0,%1,%2,%3};"
                        : "+f"(acc[i][j][0]), "+f"(acc[i][j][1]),
                          "+f"(acc[i][j][2]), "+f"(acc[i][j][3])
                        : "r"(a[i][0]), "r"(a[i][1]), "r"(a[i][2]), "r"(a[i][3]),
                          "r"(b[j][0]), "r"(b[j][1]));
        }
    }
#pragma unroll
    for (int i = 0; i < 2; i++) {
        int row = m0 + wm0 + i*16 + gid;
#pragma unroll
        for (int j = 0; j < 8; j++) {
            int col = n0 + wn0 + j*8 + tig*2;
            *(float2*)(C + (size_t)row*Ng + col)     = make_float2(acc[i][j][0], acc[i][j][1]);
            *(float2*)(C + (size_t)(row+8)*Ng + col) = make_float2(acc[i][j][2], acc[i][j][3]);
        }
    }
}

// ---------------- per-sequence fused middle ----------------
// smem layout (float indices). HT (4352) aliases XM region (reserved 4352).
#define S_XM   0        // [16][256] x_m ; later HT [i][s] stride 17
#define S_HT   0
#define S_XC   4352     // [16][256]
#define S_QT   8448     // q transposed [i][t] stride 17 (4352)
// halves (index in __half units)
#define H_K    25600    // K [t][260] half  (4160 h = 2080 f at float off 12800)
#define H_V    29760    // V transposed [i][18] half (4608 h = 2304 f at 14880)
#define S_IG   17184    // [t][4]
#define S_FG   17248    // [t][4]
#define S_LFC  17312    // [h][17]
#define S_AA   17380    // [h][16]
#define S_WM   17444    // [h][s][t] 1024
#define SM3_FLOATS 18468

__global__ void __launch_bounds__(256,3) k_seq(
    const float* __restrict__ UP,
    const float* __restrict__ conv_w, const float* __restrict__ conv_b,
    const float* __restrict__ Wq, const float* __restrict__ Wk, const float* __restrict__ Wv,
    const float* __restrict__ ig_w, const float* __restrict__ ig_b,
    const float* __restrict__ fg_w, const float* __restrict__ fg_b,
    const float* __restrict__ ln_w, const float* __restrict__ skip,
    float* __restrict__ HS) {
    extern __shared__ float sm[];
    __half* smh = (__half*)sm;
    const int tid = threadIdx.x;
    const int seq = blockIdx.x;

    // --- A: load x_m [16][256] ---
    {
        const float4* src = (const float4*)(UP + (size_t)seq * 16 * 512);
        float4* d4 = (float4*)(sm + S_XM);
        for (int i = tid; i < 1024; i += 256) {
            int row = i >> 6, q = i & 63;
            d4[row*64 + q] = src[row*128 + q];
        }
    }
    __syncthreads();

    // --- B: causal depthwise conv (K=4) + silu -> xc ---
    for (int e = tid; e < 4096; e += 256) {
        int t = e >> 8, i = e & 255;
        float a = conv_b[i];
#pragma unroll
        for (int j = 0; j < 4; j++) {
            int tt = t + j - 3;
            if (tt >= 0) a += conv_w[j*256 + i] * sm[S_XM + tt*256 + i];
        }
        sm[S_XC + t*256 + i] = siluf(a);
    }
    __syncthreads();

    // --- C: block-diagonal q,k,v ---
    for (int e = tid; e < 4096; e += 256) {
        int t = e >> 8, col = e & 255;
        int n = col >> 2, o = col & 3;
        float4 wq4 = *(const float4*)(Wq + n*16 + o*4);
        float4 wk4 = *(const float4*)(Wk + n*16 + o*4);
        float4 wv4 = *(const float4*)(Wv + n*16 + o*4);
        float4 xc4 = *(const float4*)&sm[S_XC + t*256 + n*4];
        float4 xm4 = *(const float4*)&sm[S_XM + t*256 + n*4];
        float aq = xc4.x*wq4.x + xc4.y*wq4.y + xc4.z*wq4.z + xc4.w*wq4.w;
        float ak = xc4.x*wk4.x + xc4.y*wk4.y + xc4.z*wk4.z + xc4.w*wk4.w;
        float av = xm4.x*wv4.x + xm4.y*wv4.y + xm4.z*wv4.z + xm4.w*wv4.w;
        sm[S_QT + col*17 + t]   = aq;
        smh[H_K + t*260 + col]  = __float2half(ak);
        smh[H_V + col*18 + t]   = __float2half(av);
    }
    __syncthreads();

    // --- D: gate preacts; warp tp covers (t=tp, t=tp+8), lanes split j ---
    {
        const int gc = tid & 31;
        const int tp = tid >> 5;       // 0..7
        float aI0[4]={0,0,0,0}, aF0[4]={0,0,0,0};
        float aI1[4]={0,0,0,0}, aF1[4]={0,0,0,0};
#pragma unroll
        for (int i = 0; i < 8; i++) {   // q segment
            int jj = i*32 + gc;
            float v0 = sm[S_QT + jj*17 + tp];
            float v1 = sm[S_QT + jj*17 + tp + 8];
            float4 wi = *(const float4*)(ig_w + jj*4);
            float4 wf = *(const float4*)(fg_w + jj*4);
            aI0[0]+=v0*wi.x; aI0[1]+=v0*wi.y; aI0[2]+=v0*wi.z; aI0[3]+=v0*wi.w;
            aF0[0]+=v0*wf.x; aF0[1]+=v0*wf.y; aF0[2]+=v0*wf.z; aF0[3]+=v0*wf.w;
            aI1[0]+=v1*wi.x; aI1[1]+=v1*wi.y; aI1[2]+=v1*wi.z; aI1[3]+=v1*wi.w;
            aF1[0]+=v1*wf.x; aF1[1]+=v1*wf.y; aF1[2]+=v1*wf.z; aF1[3]+=v1*wf.w;
        }
#pragma unroll
        for (int i = 0; i < 8; i++) {   // k segment
            int jc = i*32 + gc, jj = 256 + jc;
            float v0 = __half2float(smh[H_K + tp*260 + jc]);
            float v1 = __half2float(smh[H_K + (tp+8)*260 + jc]);
            float4 wi = *(const float4*)(ig_w + jj*4);
            float4 wf = *(const float4*)(fg_w + jj*4);
            aI0[0]+=v0*wi.x; aI0[1]+=v0*wi.y; aI0[2]+=v0*wi.z; aI0[3]+=v0*wi.w;
            aF0[0]+=v0*wf.x; aF0[1]+=v0*wf.y; aF0[2]+=v0*wf.z; aF0[3]+=v0*wf.w;
            aI1[0]+=v1*wi.x; aI1[1]+=v1*wi.y; aI1[2]+=v1*wi.z; aI1[3]+=v1*wi.w;
            aF1[0]+=v1*wf.x; aF1[1]+=v1*wf.y; aF1[2]+=v1*wf.z; aF1[3]+=v1*wf.w;
        }
#pragma unroll
        for (int i = 0; i < 8; i++) {   // v segment
            int jc = i*32 + gc, jj = 512 + jc;
            float v0 = __half2float(smh[H_V + jc*18 + tp]);
            float v1 = __half2float(smh[H_V + jc*18 + tp + 8]);
            float4 wi = *(const float4*)(ig_w + jj*4);
            float4 wf = *(const float4*)(fg_w + jj*4);
            aI0[0]+=v0*wi.x; aI0[1]+=v0*wi.y; aI0[2]+=v0*wi.z; aI0[3]+=v0*wi.w;
            aF0[0]+=v0*wf.x; aF0[1]+=v0*wf.y; aF0[2]+=v0*wf.z; aF0[3]+=v0*wf.w;
            aI1[0]+=v1*wi.x; aI1[1]+=v1*wi.y; aI1[2]+=v1*wi.z; aI1[3]+=v1*wi.w;
            aF1[0]+=v1*wf.x; aF1[1]+=v1*wf.y; aF1[2]+=v1*wf.z; aF1[3]+=v1*wf.w;
        }
#pragma unroll
        for (int m = 1; m < 32; m <<= 1) {
#pragma unroll
            for (int g = 0; g < 4; g++) {
                aI0[g] += __shfl_xor_sync(0xffffffffu, aI0[g], m);
                aF0[g] += __shfl_xor_sync(0xffffffffu, aF0[g], m);
                aI1[g] += __shfl_xor_sync(0xffffffffu, aI1[g], m);
                aF1[g] += __shfl_xor_sync(0xffffffffu, aF1[g], m);
            }
        }
        if (gc == 0) {
#pragma unroll
            for (int g = 0; g < 4; g++) {
                sm[S_IG + tp*4 + g]     = aI0[g] + ig_b[g];
                sm[S_FG + tp*4 + g]     = aF0[g] + fg_b[g];
                sm[S_IG + (tp+8)*4 + g] = aI1[g] + ig_b[g];
                sm[S_FG + (tp+8)*4 + g] = aF1[g] + fg_b[g];
            }
        }
    }
    __syncthreads();

    // --- E: parallel prefix scan of log-sigmoid(fg) (64 threads) ---
    if (tid < 64) {
        int h = tid >> 4, t = tid & 15;
        float fgv = sm[S_FG + t*4 + h];
        float cum = fminf(fgv, 0.f) - __logf(1.f + __expf(-fabsf(fgv)));
#pragma unroll
        for (int m = 1; m < 16; m <<= 1) {
            float o = __shfl_up_sync(0xffffffffu, cum, m, 16);
            if ((tid & 15) >= m) cum += o;
        }
        sm[S_LFC + h*17 + t + 1] = cum;
        if (t == 0) sm[S_LFC + h*17] = 0.f;
        sm[S_AA + h*16 + t] = sm[S_IG + t*4 + h] - cum;
    }
    // (no barrier yet; qk below only reads QT/K)

    // --- F1: qk ---
    const int mh = tid >> 6;
    const int ms = (tid >> 2) & 15;
    const int mtq = tid & 3;
    float qkv4[4] = {0.f, 0.f, 0.f, 0.f};
    {
        int qtb = S_QT + mh*64*17 + ms;
        int kb = H_K + mh*64;
#pragma unroll 8
        for (int dd = 0; dd < 32; dd++) {
            float q0 = sm[qtb + (2*dd)*17];
            float q1 = sm[qtb + (2*dd+1)*17];
#pragma unroll
            for (int j = 0; j < 4; j++) {
                int t = mtq*4 + j;
                __half2 kh = *(const __half2*)&smh[kb + t*260 + 2*dd];
                float2 kf = __half22float2(kh);
                qkv4[j] += q0*kf.x + q1*kf.y;
            }
        }
    }
    __syncthreads();   // E results visible

    // --- F2: D-weights + normalizer -> wm ---
    {
        float cs = sm[S_LFC + mh*17 + ms + 1];
        float mloc = -1e30f;
        float ldv[4];
#pragma unroll
        for (int j = 0; j < 4; j++) {
            int t = mtq*4 + j;
            if (t <= ms) { ldv[j] = cs + sm[S_AA + mh*16 + t]; mloc = fmaxf(mloc, ldv[j]); }
            else ldv[j] = 0.f;
        }
        mloc = fmaxf(mloc, __shfl_xor_sync(0xffffffffu, mloc, 1));
        mloc = fmaxf(mloc, __shfl_xor_sync(0xffffffffu, mloc, 2));
        float cv[4]; float csum = 0.f;
#pragma unroll
        for (int j = 0; j < 4; j++) {
            int t = mtq*4 + j;
            cv[j] = (t <= ms) ? (qkv4[j]*0.125f) * __expf(ldv[j] - mloc) : 0.f;
            csum += cv[j];
        }
        csum += __shfl_xor_sync(0xffffffffu, csum, 1);
        csum += __shfl_xor_sync(0xffffffffu, csum, 2);
        float norm = fmaxf(fabsf(csum), __expf(-mloc)) + 1e-6f;
        float inv = 1.f / norm;
#pragma unroll
        for (int j = 0; j < 4; j++)
            sm[S_WM + (mh*16 + ms)*16 + mtq*4 + j] = cv[j] * inv;
    }
    __syncthreads();

    // --- G: out = wm @ v -> HT (aliases dead XM) ---
    {
        int hC = tid >> 6, dC = tid & 63;
        int ib = H_V + (hC*64 + dC)*18;
        float vreg[16];
#pragma unroll
        for (int tp = 0; tp < 8; tp++) {
            float2 vf = __half22float2(*(const __half2*)&smh[ib + 2*tp]);
            vreg[2*tp] = vf.x; vreg[2*tp+1] = vf.y;
        }
#pragma unroll
        for (int s2 = 0; s2 < 16; s2++) {
            float a2 = 0.f;
#pragma unroll
            for (int t = 0; t < 16; t++)
                a2 += sm[S_WM + (hC*16 + s2)*16 + t] * vreg[t];
            sm[S_HT + (hC*64 + dC)*17 + s2] = a2;
        }
    }
    __syncthreads();

    // --- H: group LayerNorm + skip*xc + silu(z) gate ---
    {
        int hD = tid >> 6, sD = (tid >> 2) & 15, dq = tid & 3;
        float vals[16]; float sum = 0.f, sq = 0.f;
#pragma unroll
        for (int dd = 0; dd < 16; dd++) {
            int i = hD*64 + dq*16 + dd;
            float v = sm[S_HT + i*17 + sD];
            vals[dd] = v; sum += v; sq += v*v;
        }
        sum += __shfl_xor_sync(0xffffffffu, sum, 1);
        sum += __shfl_xor_sync(0xffffffffu, sum, 2);
        sq  += __shfl_xor_sync(0xffffffffu, sq, 1);
        sq  += __shfl_xor_sync(0xffffffffu, sq, 2);
        float mu = sum * (1.f/64.f);
        float var = sq * (1.f/64.f) - mu*mu;
        float rstd = rsqrtf(var + 1e-5f);
        const float* zrow = UP + (size_t)seq*8192 + sD*512 + 256;
#pragma unroll
        for (int dd = 0; dd < 16; dd++) {
            int i = hD*64 + dq*16 + dd;
            float hn = (vals[dd] - mu) * rstd * ln_w[i];
            float zz = zrow[i];
            float o = (hn + skip[i] * sm[S_XC + sD*256 + i]) * siluf(zz);
            sm[S_HT + i*17 + sD] = o;
        }
    }
    __syncthreads();

    // --- coalesced write HS[row][i] ---
    {
        float* dst = HS + (size_t)seq * 16 * 256;
        for (int idx = tid; idx < 4096; idx += 256) {
            int t = idx >> 8, i = idx & 255;
            dst[idx] = sm[S_HT + i*17 + t];
        }
    }
}

// ---------------- launch ----------------
extern "C" void kernel_launch(void* const* d_in, const int* in_sizes, int n_in,
                              void* d_out, int out_size) {
    const float* x      = (const float*)d_in[0];
    const float* W_up   = (const float*)d_in[1];
    const float* conv_w = (const float*)d_in[2];
    const float* conv_b = (const float*)d_in[3];
    const float* Wq     = (const float*)d_in[4];
    const float* Wk     = (const float*)d_in[5];
    const float* Wv     = (const float*)d_in[6];
    const float* ig_w   = (const float*)d_in[7];
    const float* ig_b   = (const float*)d_in[8];
    const float* fg_w   = (const float*)d_in[9];
    const float* fg_b   = (const float*)d_in[10];
    const float* ln_w   = (const float*)d_in[11];
    const float* skip   = (const float*)d_in[12];
    const float* W_down = (const float*)d_in[13];
    float* out = (float*)d_out;

    float *XS, *UP, *HS, *OT, *WTU, *WTD;
    cudaGetSymbolAddress((void**)&XS,  g_XS);
    cudaGetSymbolAddress((void**)&UP,  g_UP);
    cudaGetSymbolAddress((void**)&HS,  g_HS);
    cudaGetSymbolAddress((void**)&OT,  g_OT);
    cudaGetSymbolAddress((void**)&WTU, g_WTU);
    cudaGetSymbolAddress((void**)&WTD, g_WTD);

    cudaFuncSetAttribute(k_seq, cudaFuncAttributeMaxDynamicSharedMemorySize,
                         SM3_FLOATS * (int)sizeof(float));

    k_transpose_in<<<4096, 256>>>(x, XS);
    k_wt<<<256, 256>>>(W_up, WTU, 128, 512);
    k_wt<<<128, 256>>>(W_down, WTD, 256, 128);
    // up: C[131072,512] = XS[131072,128] @ WTU[512,128]^T
    k_gemm_mma<<<dim3(4, 1024), 256>>>(XS, WTU, UP, 512, 128);
    k_seq<<<SEQS, 256, SM3_FLOATS * sizeof(float)>>>(UP, conv_w, conv_b,
        Wq, Wk, Wv, ig_w, ig_b, fg_w, fg_b, ln_w, skip, HS);
    // down: C[131072,128] = HS[131072,256] @ WTD[128,256]^T
    k_gemm_mma<<<dim3(1, 1024), 256>>>(HS, WTD, OT, 128, 256);
    k_transpose_out<<<4096, 256>>>(OT, out);
}

// round 7
// speedup vs baseline: 3.1281x; 1.0744x over previous
#include <cuda_runtime.h>
#include <cuda_fp16.h>
#include <cstdint>
#include <math.h>

// ---------------- problem constants ----------------
#define DIMC  128
#define TT    16
#define INNER 256
#define SEQS  8192
#define ROWS  (SEQS*TT)         // 131072
#define UPCOLS 512

// ---------------- scratch (static device, no allocs) ----------------
__device__ __half g_XS[(size_t)ROWS*DIMC];   // [row][128] fp16
__device__ float  g_UP[(size_t)ROWS*UPCOLS]; // [row][512] fp32
__device__ __half g_HS[(size_t)ROWS*INNER];  // [row][256] fp16
__device__ float  g_OT[(size_t)ROWS*DIMC];   // [row][128] fp32
__device__ __half g_WTU[512*128];            // W_up^T  [n][k] fp16
__device__ __half g_WTD[128*256];            // W_down^T [n][k] fp16

// ---------------- helpers ----------------
__device__ __forceinline__ float siluf(float x){ return x / (1.f + __expf(-x)); }
__device__ __forceinline__ uint32_t smem_u32(const void* p){
    uint32_t a;
    asm("{ .reg .u64 t; cvta.to.shared.u64 t, %1; cvt.u32.u64 %0, t; }" : "=r"(a) : "l"(p));
    return a;
}

// ---------------- kernel: (b,c,t,h,w) -> XS[seq][t][c] (fp16) ----------------
__global__ void __launch_bounds__(256) k_transpose_in(const float* __restrict__ x,
                                                      __half* __restrict__ XS) {
    __shared__ float tile[128*33];
    int bid = blockIdx.x;
    int b = bid >> 9;
    int t = (bid >> 5) & 15;
    int h = bid & 31;
    const float* src = x + ((size_t)(b*128)*16 + t) * 1024 + h*32;
    for (int idx = threadIdx.x; idx < 128*32; idx += 256) {
        int c = idx >> 5, w = idx & 31;
        tile[c*33 + w] = src[(size_t)c*16384 + w];
    }
    __syncthreads();
    size_t base = ((size_t)(b*1024 + h*32) * 16 + t) * 128;
    for (int idx = threadIdx.x; idx < 2048; idx += 256) {
        int w = idx >> 6, c2 = idx & 63;
        __half2 v = __float22half2_rn(make_float2(tile[(2*c2)*33 + w],
                                                  tile[(2*c2+1)*33 + w]));
        *(__half2*)(XS + base + (size_t)w*2048 + 2*c2) = v;
    }
}

// ---------------- kernel: OT[row][c] -> out (b,c,t,h,w) ----------------
__global__ void __launch_bounds__(256) k_transpose_out(const float* __restrict__ OT,
                                                       float* __restrict__ out) {
    __shared__ float tile[128*33];
    int bid = blockIdx.x;
    int b = bid >> 9;
    int t = (bid >> 5) & 15;
    int h = bid & 31;
    size_t base = ((size_t)(b*1024 + h*32) * 16 + t) * 128;
    for (int idx = threadIdx.x; idx < 32*128; idx += 256) {
        int w = idx >> 7, c = idx & 127;
        tile[c*33 + w] = OT[base + (size_t)w*2048 + c];
    }
    __syncthreads();
    float* dst = out + ((size_t)(b*128)*16 + t) * 1024 + h*32;
    for (int idx = threadIdx.x; idx < 128*32; idx += 256) {
        int c = idx >> 5, w = idx & 31;
        dst[(size_t)c*16384 + w] = tile[c*33 + w];
    }
}

// ---------------- weight transpose to fp16: Wt[n][k] = W[k][n] ----------------
__global__ void k_wt(const float* __restrict__ W, __half* __restrict__ Wt, int K, int N){
    int idx = blockIdx.x*256 + threadIdx.x;
    if (idx < K*N) { int k = idx / N, n = idx - k*N; Wt[(size_t)n*K + k] = __float2half(W[idx]); }
}

// ---------------- fp16 warp-MMA GEMM: C[M,Ng] = A[M,K] @ Bt[Ng,K]^T ----------------
// CTA 128x128, BK=32 halves, cp.async double-buffered, m16n8k16, fp32 accum.
// smem row stride 40 halves (80B = 5x16B aligned; h2-stride 20 -> conflict-free frags).
__global__ void __launch_bounds__(256) k_gemm_h(const __half* __restrict__ A,
        const __half* __restrict__ Bt, float* __restrict__ C, int Ng, int Kf) {
    __shared__ __align__(16) __half As[2][128*40];
    __shared__ __align__(16) __half Bs[2][128*40];
    const int tid  = threadIdx.x;
    const int lane = tid & 31, warp = tid >> 5;
    const int gid  = lane >> 2, tig = lane & 3;
    const int wm0  = (warp >> 1) * 32;
    const int wn0  = (warp & 1) * 64;
    const int m0 = blockIdx.y * 128, n0 = blockIdx.x * 128;
    const int nk = Kf >> 5;

    uint32_t sA0 = smem_u32(As[0]), sA1 = smem_u32(As[1]);
    uint32_t sB0 = smem_u32(Bs[0]), sB1 = smem_u32(Bs[1]);

    float acc[2][8][4];
#pragma unroll
    for (int i = 0; i < 2; i++)
#pragma unroll
        for (int j = 0; j < 8; j++)
#pragma unroll
            for (int e = 0; e < 4; e++) acc[i][j][e] = 0.f;

    auto issue = [&](int kb, int buf){
        uint32_t da_base = buf ? sA1 : sA0;
        uint32_t db_base = buf ? sB1 : sB0;
#pragma unroll
        for (int r = 0; r < 2; r++) {
            int idx = tid + 256*r;
            int row = idx >> 2, c16 = idx & 3;
            const __half* ga = A  + (size_t)(m0+row)*Kf + kb + c16*8;
            const __half* gb = Bt + (size_t)(n0+row)*Kf + kb + c16*8;
            uint32_t da = da_base + row*80 + c16*16;
            uint32_t db = db_base + row*80 + c16*16;
            asm volatile("cp.async.cg.shared.global [%0], [%1], 16;" :: "r"(da), "l"(ga));
            asm volatile("cp.async.cg.shared.global [%0], [%1], 16;" :: "r"(db), "l"(gb));
        }
        asm volatile("cp.async.commit_group;");
    };

    issue(0, 0);
    for (int kc = 0; kc < nk; kc++) {
        if (kc + 1 < nk) {
            issue((kc+1)*32, (kc+1)&1);
            asm volatile("cp.async.wait_group 1;");
        } else {
            asm volatile("cp.async.wait_group 0;");
        }
        __syncthreads();
        const __half2* A2 = (const __half2*)As[kc&1];
        const __half2* B2 = (const __half2*)Bs[kc&1];
#pragma unroll
        for (int ks = 0; ks < 2; ks++) {
            const int k2b = ks*8;
            uint32_t a[2][4], b[8][2];
#pragma unroll
            for (int i = 0; i < 2; i++) {
                int r = wm0 + i*16 + gid;
                a[i][0] = *(const uint32_t*)&A2[r*20 + k2b + tig];
                a[i][1] = *(const uint32_t*)&A2[(r+8)*20 + k2b + tig];
                a[i][2] = *(const uint32_t*)&A2[r*20 + k2b + tig + 4];
                a[i][3] = *(const uint32_t*)&A2[(r+8)*20 + k2b + tig + 4];
            }
#pragma unroll
            for (int j = 0; j < 8; j++) {
                int rn = wn0 + j*8 + gid;
                b[j][0] = *(const uint32_t*)&B2[rn*20 + k2b + tig];
                b[j][1] = *(const uint32_t*)&B2[rn*20 + k2b + tig + 4];
            }
#pragma unroll
            for (int i = 0; i < 2; i++)
#pragma unroll
                for (int j = 0; j < 8; j++)
                    asm volatile(
                        "mma.sync.aligned.m16n8k16.row.col.f32.f16.f16.f32 "
                        "{%0,%1,%2,%3}, {%4,%5,%6,%7}, {%8,%9}, {%0,%1,%2,%3};"
                        : "+f"(acc[i][j][0]), "+f"(acc[i][j][1]),
                          "+f"(acc[i][j][2]), "+f"(acc[i][j][3])
                        : "r"(a[i][0]), "r"(a[i][1]), "r"(a[i][2]), "r"(a[i][3]),
                          "r"(b[j][0]), "r"(b[j][1]));
        }
        __syncthreads();
    }
#pragma unroll
    for (int i = 0; i < 2; i++) {
        int row = m0 + wm0 + i*16 + gid;
#pragma unroll
        for (int j = 0; j < 8; j++) {
            int col = n0 + wn0 + j*8 + tig*2;
            *(float2*)(C + (size_t)row*Ng + col)     = make_float2(acc[i][j][0], acc[i][j][1]);
            *(float2*)(C + (size_t)(row+8)*Ng + col) = make_float2(acc[i][j][2], acc[i][j][3]);
        }
    }
}

// ---------------- per-sequence fused middle ----------------
// smem layout (float indices). HT (4352) aliases XM region (reserved 4352).
#define S_XM   0        // [16][256] x_m ; later HT [i][s] stride 17
#define S_HT   0
#define S_XC   4352     // [16][256]
#define S_QT   8448     // q transposed [i][t] stride 17 (4352)
// halves (index in __half units)
#define H_K    25600    // K [t][260] half
#define H_V    29760    // V transposed [i][18] half
#define S_IG   17184    // [t][4]
#define S_FG   17248    // [t][4]
#define S_LFC  17312    // [h][17]
#define S_AA   17380    // [h][16]
#define S_WM   17444    // [h][s][t] 1024
#define SM3_FLOATS 18468

__global__ void __launch_bounds__(256,3) k_seq(
    const float* __restrict__ UP,
    const float* __restrict__ conv_w, const float* __restrict__ conv_b,
    const float* __restrict__ Wq, const float* __restrict__ Wk, const float* __restrict__ Wv,
    const float* __restrict__ ig_w, const float* __restrict__ ig_b,
    const float* __restrict__ fg_w, const float* __restrict__ fg_b,
    const float* __restrict__ ln_w, const float* __restrict__ skip,
    __half* __restrict__ HS) {
    extern __shared__ float sm[];
    __half* smh = (__half*)sm;
    const int tid = threadIdx.x;
    const int seq = blockIdx.x;

    // --- A: load x_m [16][256] ---
    {
        const float4* src = (const float4*)(UP + (size_t)seq * 16 * 512);
        float4* d4 = (float4*)(sm + S_XM);
        for (int i = tid; i < 1024; i += 256) {
            int row = i >> 6, q = i & 63;
            d4[row*64 + q] = src[row*128 + q];
        }
    }
    __syncthreads();

    // --- BC: fused conv+silu -> xc, then block-diagonal q,k,v ---
#pragma unroll
    for (int r = 0; r < 4; r++) {
        int e = tid + 256*r;          // 0..1023
        int t = e >> 6, n = e & 63;
        float4 a4 = *(const float4*)(conv_b + n*4);
        float4 xm_t = make_float4(0.f,0.f,0.f,0.f);
#pragma unroll
        for (int j = 0; j < 4; j++) {
            int tt = t + j - 3;
            if (tt >= 0) {
                float4 cw = *(const float4*)(conv_w + j*256 + n*4);
                float4 xm = *(const float4*)&sm[S_XM + tt*256 + n*4];
                a4.x += cw.x*xm.x; a4.y += cw.y*xm.y;
                a4.z += cw.z*xm.z; a4.w += cw.w*xm.w;
                if (j == 3) xm_t = xm;
            }
        }
        float4 xc;
        xc.x = siluf(a4.x); xc.y = siluf(a4.y);
        xc.z = siluf(a4.z); xc.w = siluf(a4.w);
        *(float4*)&sm[S_XC + t*256 + n*4] = xc;
        float qv[4], kv[4], vv[4];
#pragma unroll
        for (int o = 0; o < 4; o++) {
            float4 wq = *(const float4*)(Wq + n*16 + o*4);
            float4 wk = *(const float4*)(Wk + n*16 + o*4);
            float4 wv = *(const float4*)(Wv + n*16 + o*4);
            qv[o] = xc.x*wq.x + xc.y*wq.y + xc.z*wq.z + xc.w*wq.w;
            kv[o] = xc.x*wk.x + xc.y*wk.y + xc.z*wk.z + xc.w*wk.w;
            vv[o] = xm_t.x*wv.x + xm_t.y*wv.y + xm_t.z*wv.z + xm_t.w*wv.w;
        }
#pragma unroll
        for (int o = 0; o < 4; o++) {
            sm[S_QT + (n*4+o)*17 + t] = qv[o];
            smh[H_V + (n*4+o)*18 + t] = __float2half(vv[o]);
        }
        *(__half2*)&smh[H_K + t*260 + n*4]     = __float22half2_rn(make_float2(kv[0], kv[1]));
        *(__half2*)&smh[H_K + t*260 + n*4 + 2] = __float22half2_rn(make_float2(kv[2], kv[3]));
    }
    __syncthreads();

    // --- D: gate preacts; warp tp covers (t=tp, t=tp+8), lanes split j ---
    {
        const int gc = tid & 31;
        const int tp = tid >> 5;       // 0..7
        float aI0[4]={0,0,0,0}, aF0[4]={0,0,0,0};
        float aI1[4]={0,0,0,0}, aF1[4]={0,0,0,0};
#pragma unroll
        for (int i = 0; i < 8; i++) {   // q segment
            int jj = i*32 + gc;
            float v0 = sm[S_QT + jj*17 + tp];
            float v1 = sm[S_QT + jj*17 + tp + 8];
            float4 wi = *(const float4*)(ig_w + jj*4);
            float4 wf = *(const float4*)(fg_w + jj*4);
            aI0[0]+=v0*wi.x; aI0[1]+=v0*wi.y; aI0[2]+=v0*wi.z; aI0[3]+=v0*wi.w;
            aF0[0]+=v0*wf.x; aF0[1]+=v0*wf.y; aF0[2]+=v0*wf.z; aF0[3]+=v0*wf.w;
            aI1[0]+=v1*wi.x; aI1[1]+=v1*wi.y; aI1[2]+=v1*wi.z; aI1[3]+=v1*wi.w;
            aF1[0]+=v1*wf.x; aF1[1]+=v1*wf.y; aF1[2]+=v1*wf.z; aF1[3]+=v1*wf.w;
        }
#pragma unroll
        for (int i = 0; i < 8; i++) {   // k segment
            int jc = i*32 + gc, jj = 256 + jc;
            float v0 = __half2float(smh[H_K + tp*260 + jc]);
            float v1 = __half2float(smh[H_K + (tp+8)*260 + jc]);
            float4 wi = *(const float4*)(ig_w + jj*4);
            float4 wf = *(const float4*)(fg_w + jj*4);
            aI0[0]+=v0*wi.x; aI0[1]+=v0*wi.y; aI0[2]+=v0*wi.z; aI0[3]+=v0*wi.w;
            aF0[0]+=v0*wf.x; aF0[1]+=v0*wf.y; aF0[2]+=v0*wf.z; aF0[3]+=v0*wf.w;
            aI1[0]+=v1*wi.x; aI1[1]+=v1*wi.y; aI1[2]+=v1*wi.z; aI1[3]+=v1*wi.w;
            aF1[0]+=v1*wf.x; aF1[1]+=v1*wf.y; aF1[2]+=v1*wf.z; aF1[3]+=v1*wf.w;
        }
#pragma unroll
        for (int i = 0; i < 8; i++) {   // v segment
            int jc = i*32 + gc, jj = 512 + jc;
            float v0 = __half2float(smh[H_V + jc*18 + tp]);
            float v1 = __half2float(smh[H_V + jc*18 + tp + 8]);
            float4 wi = *(const float4*)(ig_w + jj*4);
            float4 wf = *(const float4*)(fg_w + jj*4);
            aI0[0]+=v0*wi.x; aI0[1]+=v0*wi.y; aI0[2]+=v0*wi.z; aI0[3]+=v0*wi.w;
            aF0[0]+=v0*wf.x; aF0[1]+=v0*wf.y; aF0[2]+=v0*wf.z; aF0[3]+=v0*wf.w;
            aI1[0]+=v1*wi.x; aI1[1]+=v1*wi.y; aI1[2]+=v1*wi.z; aI1[3]+=v1*wi.w;
            aF1[0]+=v1*wf.x; aF1[1]+=v1*wf.y; aF1[2]+=v1*wf.z; aF1[3]+=v1*wf.w;
        }
#pragma unroll
        for (int m = 1; m < 32; m <<= 1) {
#pragma unroll
            for (int g = 0; g < 4; g++) {
                aI0[g] += __shfl_xor_sync(0xffffffffu, aI0[g], m);
                aF0[g] += __shfl_xor_sync(0xffffffffu, aF0[g], m);
                aI1[g] += __shfl_xor_sync(0xffffffffu, aI1[g], m);
                aF1[g] += __shfl_xor_sync(0xffffffffu, aF1[g], m);
            }
        }
        if (gc == 0) {
#pragma unroll
            for (int g = 0; g < 4; g++) {
                sm[S_IG + tp*4 + g]     = aI0[g] + ig_b[g];
                sm[S_FG + tp*4 + g]     = aF0[g] + fg_b[g];
                sm[S_IG + (tp+8)*4 + g] = aI1[g] + ig_b[g];
                sm[S_FG + (tp+8)*4 + g] = aF1[g] + fg_b[g];
            }
        }
    }
    __syncthreads();

    // --- E: parallel prefix scan of log-sigmoid(fg) (64 threads) ---
    if (tid < 64) {
        int h = tid >> 4, t = tid & 15;
        float fgv = sm[S_FG + t*4 + h];
        float cum = fminf(fgv, 0.f) - __logf(1.f + __expf(-fabsf(fgv)));
#pragma unroll
        for (int m = 1; m < 16; m <<= 1) {
            float o = __shfl_up_sync(0xffffffffu, cum, m, 16);
            if ((tid & 15) >= m) cum += o;
        }
        sm[S_LFC + h*17 + t + 1] = cum;
        if (t == 0) sm[S_LFC + h*17] = 0.f;
        sm[S_AA + h*16 + t] = sm[S_IG + t*4 + h] - cum;
    }
    // (no barrier yet; qk below only reads QT/K)

    // --- F1: qk ---
    const int mh = tid >> 6;
    const int ms = (tid >> 2) & 15;
    const int mtq = tid & 3;
    float qkv4[4] = {0.f, 0.f, 0.f, 0.f};
    {
        int qtb = S_QT + mh*64*17 + ms;
        int kb = H_K + mh*64;
#pragma unroll 8
        for (int dd = 0; dd < 32; dd++) {
            float q0 = sm[qtb + (2*dd)*17];
            float q1 = sm[qtb + (2*dd+1)*17];
#pragma unroll
            for (int j = 0; j < 4; j++) {
                int t = mtq*4 + j;
                __half2 kh = *(const __half2*)&smh[kb + t*260 + 2*dd];
                float2 kf = __half22float2(kh);
                qkv4[j] += q0*kf.x + q1*kf.y;
            }
        }
    }
    __syncthreads();   // E results visible

    // --- F2: D-weights + normalizer -> wm ---
    {
        float cs = sm[S_LFC + mh*17 + ms + 1];
        float mloc = -1e30f;
        float ldv[4];
#pragma unroll
        for (int j = 0; j < 4; j++) {
            int t = mtq*4 + j;
            if (t <= ms) { ldv[j] = cs + sm[S_AA + mh*16 + t]; mloc = fmaxf(mloc, ldv[j]); }
            else ldv[j] = 0.f;
        }
        mloc = fmaxf(mloc, __shfl_xor_sync(0xffffffffu, mloc, 1));
        mloc = fmaxf(mloc, __shfl_xor_sync(0xffffffffu, mloc, 2));
        float cv[4]; float csum = 0.f;
#pragma unroll
        for (int j = 0; j < 4; j++) {
            int t = mtq*4 + j;
            cv[j] = (t <= ms) ? (qkv4[j]*0.125f) * __expf(ldv[j] - mloc) : 0.f;
            csum += cv[j];
        }
        csum += __shfl_xor_sync(0xffffffffu, csum, 1);
        csum += __shfl_xor_sync(0xffffffffu, csum, 2);
        float norm = fmaxf(fabsf(csum), __expf(-mloc)) + 1e-6f;
        float inv = 1.f / norm;
#pragma unroll
        for (int j = 0; j < 4; j++)
            sm[S_WM + (mh*16 + ms)*16 + mtq*4 + j] = cv[j] * inv;
    }
    __syncthreads();

    // --- G: out = wm @ v -> HT (aliases dead XM) ---
    {
        int hC = tid >> 6, dC = tid & 63;
        int ib = H_V + (hC*64 + dC)*18;
        float vreg[16];
#pragma unroll
        for (int tp = 0; tp < 8; tp++) {
            float2 vf = __half22float2(*(const __half2*)&smh[ib + 2*tp]);
            vreg[2*tp] = vf.x; vreg[2*tp+1] = vf.y;
        }
#pragma unroll
        for (int s2 = 0; s2 < 16; s2++) {
            float a2 = 0.f;
#pragma unroll
            for (int t = 0; t < 16; t++)
                a2 += sm[S_WM + (hC*16 + s2)*16 + t] * vreg[t];
            sm[S_HT + (hC*64 + dC)*17 + s2] = a2;
        }
    }
    __syncthreads();

    // --- H: group LayerNorm + skip*xc + silu(z) gate ---
    {
        int hD = tid >> 6, sD = (tid >> 2) & 15, dq = tid & 3;
        float vals[16]; float sum = 0.f, sq = 0.f;
#pragma unroll
        for (int dd = 0; dd < 16; dd++) {
            int i = hD*64 + dq*16 + dd;
            float v = sm[S_HT + i*17 + sD];
            vals[dd] = v; sum += v; sq += v*v;
        }
        sum += __shfl_xor_sync(0xffffffffu, sum, 1);
        sum += __shfl_xor_sync(0xffffffffu, sum, 2);
        sq  += __shfl_xor_sync(0xffffffffu, sq, 1);
        sq  += __shfl_xor_sync(0xffffffffu, sq, 2);
        float mu = sum * (1.f/64.f);
        float var = sq * (1.f/64.f) - mu*mu;
        float rstd = rsqrtf(var + 1e-5f);
        const float* zrow = UP + (size_t)seq*8192 + sD*512 + 256;
#pragma unroll
        for (int dd = 0; dd < 16; dd++) {
            int i = hD*64 + dq*16 + dd;
            float hn = (vals[dd] - mu) * rstd * ln_w[i];
            float zz = zrow[i];
            float o = (hn + skip[i] * sm[S_XC + sD*256 + i]) * siluf(zz);
            sm[S_HT + i*17 + sD] = o;
        }
    }
    __syncthreads();

    // --- coalesced write HS[row][i] (fp16) ---
    {
        __half2* dst = (__half2*)(HS + (size_t)seq * 16 * 256);
        for (int idx = tid; idx < 2048; idx += 256) {
            int t = idx >> 7, i2 = idx & 127;
            float v0 = sm[S_HT + (2*i2)*17 + t];
            float v1 = sm[S_HT + (2*i2+1)*17 + t];
            dst[idx] = __float22half2_rn(make_float2(v0, v1));
        }
    }
}

// ---------------- launch ----------------
extern "C" void kernel_launch(void* const* d_in, const int* in_sizes, int n_in,
                              void* d_out, int out_size) {
    const float* x      = (const float*)d_in[0];
    const float* W_up   = (const float*)d_in[1];
    const float* conv_w = (const float*)d_in[2];
    const float* conv_b = (const float*)d_in[3];
    const float* Wq     = (const float*)d_in[4];
    const float* Wk     = (const float*)d_in[5];
    const float* Wv     = (const float*)d_in[6];
    const float* ig_w   = (const float*)d_in[7];
    const float* ig_b   = (const float*)d_in[8];
    const float* fg_w   = (const float*)d_in[9];
    const float* fg_b   = (const float*)d_in[10];
    const float* ln_w   = (const float*)d_in[11];
    const float* skip   = (const float*)d_in[12];
    const float* W_down = (const float*)d_in[13];
    float* out = (float*)d_out;

    __half *XS, *HS, *WTU, *WTD;
    float *UP, *OT;
    cudaGetSymbolAddress((void**)&XS,  g_XS);
    cudaGetSymbolAddress((void**)&UP,  g_UP);
    cudaGetSymbolAddress((void**)&HS,  g_HS);
    cudaGetSymbolAddress((void**)&OT,  g_OT);
    cudaGetSymbolAddress((void**)&WTU, g_WTU);
    cudaGetSymbolAddress((void**)&WTD, g_WTD);

    cudaFuncSetAttribute(k_seq, cudaFuncAttributeMaxDynamicSharedMemorySize,
                         SM3_FLOATS * (int)sizeof(float));

    k_transpose_in<<<4096, 256>>>(x, XS);
    k_wt<<<256, 256>>>(W_up, WTU, 128, 512);
    k_wt<<<128, 256>>>(W_down, WTD, 256, 128);
    // up: C[131072,512] = XS[131072,128] @ WTU[512,128]^T
    k_gemm_h<<<dim3(4, 1024), 256>>>(XS, WTU, UP, 512, 128);
    k_seq<<<SEQS, 256, SM3_FLOATS * sizeof(float)>>>(UP, conv_w, conv_b,
        Wq, Wk, Wv, ig_w, ig_b, fg_w, fg_b, ln_w, skip, HS);
    // down: C[131072,128] = HS[131072,256] @ WTD[128,256]^T
    k_gemm_h<<<dim3(1, 1024), 256>>>(HS, WTD, OT, 128, 256);
    k_transpose_out<<<4096, 256>>>(OT, out);
}